// round 4
// baseline (speedup 1.0000x reference)
#include <cuda_runtime.h>

// Problem constants
#define CC    768        // channels
#define NO    197        // tokens per frame (N_origin)
#define FRn   8          // FRAMES
#define BBn   8          // batch after frame-fold (64/8)
#define NNt   1576       // FRn*NO
#define HHn   12         // heads
#define HDn   64         // head dim
#define MMn   204        // gathered tokens (8 cls + 196)
#define ROWSn 12608      // BBn*NNt (= 64*197)
#define GRn   1632       // BBn*MMn

#define SMEM_ATTN (2 * MMn * HDn * 4)   // K + V tiles in fp32 = 104448 B

typedef unsigned long long ull;

// Scratch (device globals; no allocation allowed)
__device__ float g_Q[ROWSn * CC];                 // Q projection, token-major
__device__ float g_K[BBn * HHn * MMn * HDn];      // gathered K, [b][h][m][d]
__device__ float g_V[BBn * HHn * MMn * HDn];      // gathered V, [b][h][m][d]
__device__ float g_O[ROWSn * CC];                 // attention output, token-major

// ---------------------------------------------------------------------------
// Packed f32x2 helpers (Blackwell sm_100+)
// ---------------------------------------------------------------------------
#define FMA2(c, a, b) asm("fma.rn.f32x2 %0, %1, %2, %0;" : "+l"(c) : "l"(a), "l"(b))
#define ADD2(d, a, b) asm("add.rn.f32x2 %0, %1, %2;" : "=l"(d) : "l"(a), "l"(b))

__device__ __forceinline__ ull pack2_dup(float v) {
    ull r; unsigned u = __float_as_uint(v);
    asm("mov.b64 %0, {%1, %1};" : "=l"(r) : "r"(u));
    return r;
}
__device__ __forceinline__ float2 unpack2(ull v) {
    float2 f;
    asm("mov.b64 {%0, %1}, %2;" : "=f"(f.x), "=f"(f.y) : "l"(v));
    return f;
}

// token index of gathered column m (matches _build_indices_mask)
__device__ __forceinline__ int token_of(int m) {
    if (m < 8) return m * NO;            // cls tokens
    int r = m - 8;
    int f, j;
    if (r < 100) { f = r / 25; j = r - f * 25; }     // frames 0..3, len 25
    else { r -= 100; f = 4 + r / 24; j = r % 24; }   // frames 4..7, len 24
    return f * NO + 1 + f + 8 * j;
}

// ---------------------------------------------------------------------------
// Shared GEMM compute slab: 16 kk steps, 8x8 microtile via f32x2.
// accp[ip][j] packs output rows (2*ip, 2*ip+1) at column j.
// ---------------------------------------------------------------------------
__device__ __forceinline__ void mma_slab(const float (*As)[132], const float (*Bs)[132],
                                         int ty, int tx, ull accp[4][8])
{
#pragma unroll
    for (int kk = 0; kk < 16; kk++) {
        const ulonglong2 a01 = *(const ulonglong2*)&As[kk][ty * 8];
        const ulonglong2 a23 = *(const ulonglong2*)&As[kk][ty * 8 + 4];
        const float4 b0 = *(const float4*)&Bs[kk][tx * 8];
        const float4 b1 = *(const float4*)&Bs[kk][tx * 8 + 4];
        ull ap[4];
        ap[0] = a01.x; ap[1] = a01.y; ap[2] = a23.x; ap[3] = a23.y;
        ull bd[8];
        bd[0] = pack2_dup(b0.x); bd[1] = pack2_dup(b0.y);
        bd[2] = pack2_dup(b0.z); bd[3] = pack2_dup(b0.w);
        bd[4] = pack2_dup(b1.x); bd[5] = pack2_dup(b1.y);
        bd[6] = pack2_dup(b1.z); bd[7] = pack2_dup(b1.w);
#pragma unroll
        for (int ip = 0; ip < 4; ip++)
#pragma unroll
            for (int j = 0; j < 8; j++)
                FMA2(accp[ip][j], ap[ip], bd[j]);
    }
}

// store staged registers into smem tile buffer
#define STS_TILE(bufi)                                                          \
    As[bufi][lk + 0][lr] = va0.x; As[bufi][lk + 1][lr] = va0.y;                 \
    As[bufi][lk + 2][lr] = va0.z; As[bufi][lk + 3][lr] = va0.w;                 \
    As[bufi][lk + 0][lr + 64] = va1.x; As[bufi][lk + 1][lr + 64] = va1.y;       \
    As[bufi][lk + 2][lr + 64] = va1.z; As[bufi][lk + 3][lr + 64] = va1.w;       \
    Bs[bufi][lk + 0][lr] = vb0.x; Bs[bufi][lk + 1][lr] = vb0.y;                 \
    Bs[bufi][lk + 2][lr] = vb0.z; Bs[bufi][lk + 3][lr] = vb0.w;                 \
    Bs[bufi][lk + 0][lr + 64] = vb1.x; Bs[bufi][lk + 1][lr + 64] = vb1.y;       \
    Bs[bufi][lk + 2][lr + 64] = vb1.z; Bs[bufi][lk + 3][lr + 64] = vb1.w;

// ---------------------------------------------------------------------------
// GEMM 1: Q = X @ Wq^T   (12608 x 768, K=768). NT, 128x128 tile, BK=16.
// ---------------------------------------------------------------------------
__global__ __launch_bounds__(256, 2) void gemm_q_kernel(
    const float* __restrict__ A, const float* __restrict__ W)
{
    __shared__ float As[2][16][132];
    __shared__ float Bs[2][16][132];
    const int t = threadIdx.x;
    const int row0 = blockIdx.x * 128;
    const int col0 = blockIdx.y * 128;
    const int lr = t >> 2;          // 0..63
    const int lk = (t & 3) << 2;    // 0,4,8,12
    const int ty = t >> 4, tx = t & 15;

    ull accp[4][8];
#pragma unroll
    for (int i = 0; i < 4; i++)
#pragma unroll
        for (int j = 0; j < 8; j++) accp[i][j] = 0ull;

    const int r0 = row0 + lr, r1 = row0 + lr + 64;
    const int c0 = col0 + lr, c1 = col0 + lr + 64;

    float4 va0, va1, vb0, vb1;
#define LOADG_Q(k0)                                                                  \
    va0 = (r0 < ROWSn) ? *(const float4*)(A + (size_t)r0 * CC + (k0) + lk)           \
                       : make_float4(0.f, 0.f, 0.f, 0.f);                            \
    va1 = (r1 < ROWSn) ? *(const float4*)(A + (size_t)r1 * CC + (k0) + lk)           \
                       : make_float4(0.f, 0.f, 0.f, 0.f);                            \
    vb0 = *(const float4*)(W + (size_t)c0 * CC + (k0) + lk);                         \
    vb1 = *(const float4*)(W + (size_t)c1 * CC + (k0) + lk);

    LOADG_Q(0);
    STS_TILE(0);
    __syncthreads();

    int cur = 0;
    for (int k0 = 0; k0 < CC; k0 += 16) {
        if (k0 + 16 < CC) { LOADG_Q(k0 + 16); }
        mma_slab(As[cur], Bs[cur], ty, tx, accp);
        if (k0 + 16 < CC) {
            STS_TILE(cur ^ 1);
            __syncthreads();
            cur ^= 1;
        }
    }
#undef LOADG_Q

#pragma unroll
    for (int ip = 0; ip < 4; ip++) {
        float2 e[8];
#pragma unroll
        for (int j = 0; j < 8; j++) e[j] = unpack2(accp[ip][j]);
        int r = row0 + ty * 8 + 2 * ip;
        if (r < ROWSn) {
            float* dst = g_Q + (size_t)r * CC + col0 + tx * 8;
            *(float4*)(dst)     = make_float4(e[0].x, e[1].x, e[2].x, e[3].x);
            *(float4*)(dst + 4) = make_float4(e[4].x, e[5].x, e[6].x, e[7].x);
        }
        if (r + 1 < ROWSn) {
            float* dst = g_Q + (size_t)(r + 1) * CC + col0 + tx * 8;
            *(float4*)(dst)     = make_float4(e[0].y, e[1].y, e[2].y, e[3].y);
            *(float4*)(dst + 4) = make_float4(e[4].y, e[5].y, e[6].y, e[7].y);
        }
    }
}

// ---------------------------------------------------------------------------
// GEMM 2: gathered K/V projection. Rows = 1632 gathered tokens, cols = 1536.
// ---------------------------------------------------------------------------
__global__ __launch_bounds__(256, 2) void gemm_kv_kernel(
    const float* __restrict__ A, const float* __restrict__ W)
{
    __shared__ float As[2][16][132];
    __shared__ float Bs[2][16][132];
    const int t = threadIdx.x;
    const int row0 = blockIdx.x * 128;
    const int col0 = blockIdx.y * 128;
    const int lr = t >> 2;
    const int lk = (t & 3) << 2;
    const int ty = t >> 4, tx = t & 15;

    ull accp[4][8];
#pragma unroll
    for (int i = 0; i < 4; i++)
#pragma unroll
        for (int j = 0; j < 8; j++) accp[i][j] = 0ull;

    int src[2];
#pragma unroll
    for (int i = 0; i < 2; i++) {
        int gr = row0 + lr + i * 64;
        if (gr < GRn) {
            int b = gr / MMn;
            int m = gr - b * MMn;
            src[i] = b * NNt + token_of(m);
        } else src[i] = -1;
    }
    const int c0 = col0 + lr, c1 = col0 + lr + 64;

    float4 va0, va1, vb0, vb1;
#define LOADG_KV(k0)                                                                 \
    va0 = (src[0] >= 0) ? *(const float4*)(A + (size_t)src[0] * CC + (k0) + lk)      \
                        : make_float4(0.f, 0.f, 0.f, 0.f);                           \
    va1 = (src[1] >= 0) ? *(const float4*)(A + (size_t)src[1] * CC + (k0) + lk)      \
                        : make_float4(0.f, 0.f, 0.f, 0.f);                           \
    vb0 = *(const float4*)(W + (size_t)c0 * CC + (k0) + lk);                         \
    vb1 = *(const float4*)(W + (size_t)c1 * CC + (k0) + lk);

    LOADG_KV(0);
    STS_TILE(0);
    __syncthreads();

    int cur = 0;
    for (int k0 = 0; k0 < CC; k0 += 16) {
        if (k0 + 16 < CC) { LOADG_KV(k0 + 16); }
        mma_slab(As[cur], Bs[cur], ty, tx, accp);
        if (k0 + 16 < CC) {
            STS_TILE(cur ^ 1);
            __syncthreads();
            cur ^= 1;
        }
    }
#undef LOADG_KV

#pragma unroll
    for (int ip = 0; ip < 4; ip++) {
        float2 e[8];
#pragma unroll
        for (int j = 0; j < 8; j++) e[j] = unpack2(accp[ip][j]);
#pragma unroll
        for (int s = 0; s < 2; s++) {
            int gr = row0 + ty * 8 + 2 * ip + s;
            if (gr >= GRn) continue;
            int b = gr / MMn;
            int m = gr - b * MMn;
#pragma unroll
            for (int j = 0; j < 8; j++) {
                int c = col0 + tx * 8 + j;
                float val = s ? e[j].y : e[j].x;
                if (c < 768) {
                    int h = c >> 6, d = c & 63;
                    g_K[(((size_t)b * HHn + h) * MMn + m) * HDn + d] = val;
                } else {
                    int c2 = c - 768;
                    int h = c2 >> 6, d = c2 & 63;
                    g_V[(((size_t)b * HHn + h) * MMn + m) * HDn + d] = val;
                }
            }
        }
    }
}

// ---------------------------------------------------------------------------
// Attention: 2 threads per query row (each owns 32 of 64 head-dims), K/V in
// SMEM, mask-scaled logits, expf without max tracking (logits are bounded).
// Block = 256 threads = 128 queries. Grid = (96 bh, 13 q-tiles).
// ---------------------------------------------------------------------------
__global__ __launch_bounds__(256, 2) void attn_kernel()
{
    extern __shared__ float sm[];
    float* Ks = sm;
    float* Vs = sm + MMn * HDn;
    const int bh = blockIdx.x;                   // 0..95 = b*12+h
    const float* Kg = g_K + (size_t)bh * MMn * HDn;
    const float* Vg = g_V + (size_t)bh * MMn * HDn;

    for (int i = threadIdx.x; i < MMn * HDn / 4; i += 256) {
        ((float4*)Ks)[i] = ((const float4*)Kg)[i];
        ((float4*)Vs)[i] = ((const float4*)Vg)[i];
    }
    __syncthreads();

    const int half = threadIdx.x & 1;
    const int n = blockIdx.y * 128 + (threadIdx.x >> 1);
    const bool valid = (n < NNt);
    const int nc = valid ? n : (NNt - 1);        // clamp; pair stays in lockstep
    const int b = bh / HHn, h = bh % HHn;
    const int frame = nc / NO;
    const int cs = (frame < 4) ? (8 + 25 * frame) : (108 + 24 * (frame - 4));
    const int ce = cs + ((frame < 4) ? 25 : 24);

    // my 32 head-dims of q, packed
    ull qp[16];
    {
        const ulonglong2* q2 = (const ulonglong2*)(g_Q + (size_t)(b * NNt + nc) * CC
                                                   + h * HDn + half * 32);
#pragma unroll
        for (int i = 0; i < 8; i++) { ulonglong2 v = q2[i]; qp[2 * i] = v.x; qp[2 * i + 1] = v.y; }
    }
    ull accp[16];
#pragma unroll
    for (int i = 0; i < 16; i++) accp[i] = 0ull;   // (0.f, 0.f)
    float den = 0.f;

    for (int m = 0; m < MMn; m++) {
        // partial dot over my 32 dims
        const ulonglong2* k2 = (const ulonglong2*)(Ks + m * HDn + half * 32);
        ull s0 = 0ull, s1 = 0ull;
#pragma unroll
        for (int i = 0; i < 8; i++) {
            ulonglong2 kv = k2[i];
            FMA2(s0, qp[2 * i], kv.x);
            FMA2(s1, qp[2 * i + 1], kv.y);
        }
        ull sc; ADD2(sc, s0, s1);
        float2 sf = unpack2(sc);
        float sh = sf.x + sf.y;
        float s = sh + __shfl_xor_sync(0xffffffffu, sh, 1);   // full 64-dim dot

        // (q.k * 0.125) * mask{1.0, 0.8}
        float mult = (m < 8 || (m >= cs && m < ce)) ? 0.125f : 0.1f;
        float p = __expf(s * mult);
        den += p;
        ull pd = pack2_dup(p);

        const ulonglong2* v2 = (const ulonglong2*)(Vs + m * HDn + half * 32);
#pragma unroll
        for (int i = 0; i < 8; i++) {
            ulonglong2 vv = v2[i];
            FMA2(accp[2 * i], pd, vv.x);
            FMA2(accp[2 * i + 1], pd, vv.y);
        }
    }

    if (valid) {
        float inv = 1.f / den;
        float* o = g_O + (size_t)(b * NNt + n) * CC + h * HDn + half * 32;
#pragma unroll
        for (int i = 0; i < 8; i++) {
            float2 e0 = unpack2(accp[2 * i]);
            float2 e1 = unpack2(accp[2 * i + 1]);
            ((float4*)o)[i] = make_float4(e0.x * inv, e0.y * inv, e1.x * inv, e1.y * inv);
        }
    }
}

// ---------------------------------------------------------------------------
// GEMM 3: out = g_O @ proj_w^T + proj_b   (12608 x 768, K=768)
// ---------------------------------------------------------------------------
__global__ __launch_bounds__(256, 2) void gemm_proj_kernel(
    const float* __restrict__ W, const float* __restrict__ bias,
    float* __restrict__ Cout)
{
    __shared__ float As[2][16][132];
    __shared__ float Bs[2][16][132];
    const int t = threadIdx.x;
    const int row0 = blockIdx.x * 128;
    const int col0 = blockIdx.y * 128;
    const int lr = t >> 2;
    const int lk = (t & 3) << 2;
    const int ty = t >> 4, tx = t & 15;
    const float* A = g_O;

    ull accp[4][8];
#pragma unroll
    for (int i = 0; i < 4; i++)
#pragma unroll
        for (int j = 0; j < 8; j++) accp[i][j] = 0ull;

    const int r0 = row0 + lr, r1 = row0 + lr + 64;
    const int c0 = col0 + lr, c1 = col0 + lr + 64;

    float4 va0, va1, vb0, vb1;
#define LOADG_P(k0)                                                                  \
    va0 = (r0 < ROWSn) ? *(const float4*)(A + (size_t)r0 * CC + (k0) + lk)           \
                       : make_float4(0.f, 0.f, 0.f, 0.f);                            \
    va1 = (r1 < ROWSn) ? *(const float4*)(A + (size_t)r1 * CC + (k0) + lk)           \
                       : make_float4(0.f, 0.f, 0.f, 0.f);                            \
    vb0 = *(const float4*)(W + (size_t)c0 * CC + (k0) + lk);                         \
    vb1 = *(const float4*)(W + (size_t)c1 * CC + (k0) + lk);

    LOADG_P(0);
    STS_TILE(0);
    __syncthreads();

    int cur = 0;
    for (int k0 = 0; k0 < CC; k0 += 16) {
        if (k0 + 16 < CC) { LOADG_P(k0 + 16); }
        mma_slab(As[cur], Bs[cur], ty, tx, accp);
        if (k0 + 16 < CC) {
            STS_TILE(cur ^ 1);
            __syncthreads();
            cur ^= 1;
        }
    }
#undef LOADG_P

    float bv[8];
#pragma unroll
    for (int j = 0; j < 8; j++) bv[j] = bias[col0 + tx * 8 + j];

#pragma unroll
    for (int ip = 0; ip < 4; ip++) {
        float2 e[8];
#pragma unroll
        for (int j = 0; j < 8; j++) e[j] = unpack2(accp[ip][j]);
        int r = row0 + ty * 8 + 2 * ip;
        if (r < ROWSn) {
            float* dst = Cout + (size_t)r * CC + col0 + tx * 8;
            *(float4*)(dst)     = make_float4(e[0].x + bv[0], e[1].x + bv[1],
                                              e[2].x + bv[2], e[3].x + bv[3]);
            *(float4*)(dst + 4) = make_float4(e[4].x + bv[4], e[5].x + bv[5],
                                              e[6].x + bv[6], e[7].x + bv[7]);
        }
        if (r + 1 < ROWSn) {
            float* dst = Cout + (size_t)(r + 1) * CC + col0 + tx * 8;
            *(float4*)(dst)     = make_float4(e[0].y + bv[0], e[1].y + bv[1],
                                              e[2].y + bv[2], e[3].y + bv[3]);
            *(float4*)(dst + 4) = make_float4(e[4].y + bv[4], e[5].y + bv[5],
                                              e[6].y + bv[6], e[7].y + bv[7]);
        }
    }
}

// ---------------------------------------------------------------------------
extern "C" void kernel_launch(void* const* d_in, const int* in_sizes, int n_in,
                              void* d_out, int out_size)
{
    const float* x      = (const float*)d_in[0];
    const float* qkv_w  = (const float*)d_in[1];
    const float* proj_w = (const float*)d_in[2];
    const float* proj_b = (const float*)d_in[3];
    float* out = (float*)d_out;

    cudaFuncSetAttribute(attn_kernel,
                         cudaFuncAttributeMaxDynamicSharedMemorySize, SMEM_ATTN);

    dim3 blk(256);
    // Q projection: 12608 x 768
    gemm_q_kernel<<<dim3(99, 6), blk>>>(x, qkv_w);
    // gathered K/V projection: 1632 x 1536 (uses qkv_w rows 768..2303)
    gemm_kv_kernel<<<dim3(13, 12), blk>>>(x, qkv_w + 768 * CC);
    // attention: 96 (b,h) blocks x 13 query tiles of 128
    attn_kernel<<<dim3(96, 13), blk, SMEM_ATTN>>>();
    // output projection + bias: 12608 x 768
    gemm_proj_kernel<<<dim3(99, 6), blk>>>(proj_w, proj_b, out);
}

// round 6
// speedup vs baseline: 1.1806x; 1.1806x over previous
#include <cuda_runtime.h>

// Problem constants
#define CC    768        // channels
#define NO    197        // tokens per frame (N_origin)
#define FRn   8          // FRAMES
#define BBn   8          // batch after frame-fold (64/8)
#define NNt   1576       // FRn*NO
#define HHn   12         // heads
#define HDn   64         // head dim
#define MMn   204        // gathered tokens (8 cls + 196)
#define ROWSn 12608      // BBn*NNt (= 64*197)
#define GRn   1632       // BBn*MMn

#define SMEM_ATTN (2 * MMn * HDn * 4)   // K + V tiles in fp32 = 104448 B

typedef unsigned long long ull;

// Scratch (device globals; no allocation allowed)
__device__ float g_Q[ROWSn * CC];                 // Q projection, token-major
__device__ float g_K[BBn * HHn * MMn * HDn];      // gathered K, [b][h][m][d]
__device__ float g_V[BBn * HHn * MMn * HDn];      // gathered V, [b][h][m][d]
__device__ float g_O[ROWSn * CC];                 // attention output, token-major

// ---------------------------------------------------------------------------
// Packed f32x2 helpers (Blackwell sm_100+)
// ---------------------------------------------------------------------------
#define FMA2(c, a, b) asm("fma.rn.f32x2 %0, %1, %2, %0;" : "+l"(c) : "l"(a), "l"(b))
#define ADD2(d, a, b) asm("add.rn.f32x2 %0, %1, %2;" : "=l"(d) : "l"(a), "l"(b))

__device__ __forceinline__ ull pack2_dup(float v) {
    ull r; unsigned u = __float_as_uint(v);
    asm("mov.b64 %0, {%1, %1};" : "=l"(r) : "r"(u));
    return r;
}
__device__ __forceinline__ float2 unpack2(ull v) {
    float2 f;
    asm("mov.b64 {%0, %1}, %2;" : "=f"(f.x), "=f"(f.y) : "l"(v));
    return f;
}

// token index of gathered column m (matches _build_indices_mask)
__device__ __forceinline__ int token_of(int m) {
    if (m < 8) return m * NO;            // cls tokens
    int r = m - 8;
    int f, j;
    if (r < 100) { f = r / 25; j = r - f * 25; }     // frames 0..3, len 25
    else { r -= 100; f = 4 + r / 24; j = r % 24; }   // frames 4..7, len 24
    return f * NO + 1 + f + 8 * j;
}

// ---------------------------------------------------------------------------
// Shared GEMM compute slab: 16 kk steps, 8x8 microtile via f32x2.
// accp[ip][j] packs output rows (2*ip, 2*ip+1) at column j.
// ---------------------------------------------------------------------------
__device__ __forceinline__ void mma_slab(const float (*As)[132], const float (*Bs)[132],
                                         int ty, int tx, ull accp[4][8])
{
#pragma unroll
    for (int kk = 0; kk < 16; kk++) {
        const ulonglong2 a01 = *(const ulonglong2*)&As[kk][ty * 8];
        const ulonglong2 a23 = *(const ulonglong2*)&As[kk][ty * 8 + 4];
        const float4 b0 = *(const float4*)&Bs[kk][tx * 8];
        const float4 b1 = *(const float4*)&Bs[kk][tx * 8 + 4];
        ull ap[4];
        ap[0] = a01.x; ap[1] = a01.y; ap[2] = a23.x; ap[3] = a23.y;
        ull bd[8];
        bd[0] = pack2_dup(b0.x); bd[1] = pack2_dup(b0.y);
        bd[2] = pack2_dup(b0.z); bd[3] = pack2_dup(b0.w);
        bd[4] = pack2_dup(b1.x); bd[5] = pack2_dup(b1.y);
        bd[6] = pack2_dup(b1.z); bd[7] = pack2_dup(b1.w);
#pragma unroll
        for (int ip = 0; ip < 4; ip++)
#pragma unroll
            for (int j = 0; j < 8; j++)
                FMA2(accp[ip][j], ap[ip], bd[j]);
    }
}

// store staged registers into smem tile buffer
#define STS_TILE(bufi)                                                          \
    As[bufi][lk + 0][lr] = va0.x; As[bufi][lk + 1][lr] = va0.y;                 \
    As[bufi][lk + 2][lr] = va0.z; As[bufi][lk + 3][lr] = va0.w;                 \
    As[bufi][lk + 0][lr + 64] = va1.x; As[bufi][lk + 1][lr + 64] = va1.y;       \
    As[bufi][lk + 2][lr + 64] = va1.z; As[bufi][lk + 3][lr + 64] = va1.w;       \
    Bs[bufi][lk + 0][lr] = vb0.x; Bs[bufi][lk + 1][lr] = vb0.y;                 \
    Bs[bufi][lk + 2][lr] = vb0.z; Bs[bufi][lk + 3][lr] = vb0.w;                 \
    Bs[bufi][lk + 0][lr + 64] = vb1.x; Bs[bufi][lk + 1][lr + 64] = vb1.y;       \
    Bs[bufi][lk + 2][lr + 64] = vb1.z; Bs[bufi][lk + 3][lr + 64] = vb1.w;

// ---------------------------------------------------------------------------
// GEMM 1: Q = X @ Wq^T   (12608 x 768, K=768). NT, 128x128 tile, BK=16.
// ---------------------------------------------------------------------------
__global__ __launch_bounds__(256, 2) void gemm_q_kernel(
    const float* __restrict__ A, const float* __restrict__ W)
{
    __shared__ float As[2][16][132];
    __shared__ float Bs[2][16][132];
    const int t = threadIdx.x;
    const int row0 = blockIdx.x * 128;
    const int col0 = blockIdx.y * 128;
    const int lr = t >> 2;          // 0..63
    const int lk = (t & 3) << 2;    // 0,4,8,12
    const int ty = t >> 4, tx = t & 15;

    ull accp[4][8];
#pragma unroll
    for (int i = 0; i < 4; i++)
#pragma unroll
        for (int j = 0; j < 8; j++) accp[i][j] = 0ull;

    const int r0 = row0 + lr, r1 = row0 + lr + 64;
    const int c0 = col0 + lr, c1 = col0 + lr + 64;

    float4 va0, va1, vb0, vb1;
#define LOADG_Q(k0)                                                                  \
    va0 = (r0 < ROWSn) ? *(const float4*)(A + (size_t)r0 * CC + (k0) + lk)           \
                       : make_float4(0.f, 0.f, 0.f, 0.f);                            \
    va1 = (r1 < ROWSn) ? *(const float4*)(A + (size_t)r1 * CC + (k0) + lk)           \
                       : make_float4(0.f, 0.f, 0.f, 0.f);                            \
    vb0 = *(const float4*)(W + (size_t)c0 * CC + (k0) + lk);                         \
    vb1 = *(const float4*)(W + (size_t)c1 * CC + (k0) + lk);

    LOADG_Q(0);
    STS_TILE(0);
    __syncthreads();

    int cur = 0;
    for (int k0 = 0; k0 < CC; k0 += 16) {
        if (k0 + 16 < CC) { LOADG_Q(k0 + 16); }
        mma_slab(As[cur], Bs[cur], ty, tx, accp);
        if (k0 + 16 < CC) {
            STS_TILE(cur ^ 1);
            __syncthreads();
            cur ^= 1;
        }
    }
#undef LOADG_Q

#pragma unroll
    for (int ip = 0; ip < 4; ip++) {
        float2 e[8];
#pragma unroll
        for (int j = 0; j < 8; j++) e[j] = unpack2(accp[ip][j]);
        int r = row0 + ty * 8 + 2 * ip;
        if (r < ROWSn) {
            float* dst = g_Q + (size_t)r * CC + col0 + tx * 8;
            *(float4*)(dst)     = make_float4(e[0].x, e[1].x, e[2].x, e[3].x);
            *(float4*)(dst + 4) = make_float4(e[4].x, e[5].x, e[6].x, e[7].x);
        }
        if (r + 1 < ROWSn) {
            float* dst = g_Q + (size_t)(r + 1) * CC + col0 + tx * 8;
            *(float4*)(dst)     = make_float4(e[0].y, e[1].y, e[2].y, e[3].y);
            *(float4*)(dst + 4) = make_float4(e[4].y, e[5].y, e[6].y, e[7].y);
        }
    }
}

// ---------------------------------------------------------------------------
// GEMM 2: gathered K/V projection. Rows = 1632 gathered tokens, cols = 1536.
// ---------------------------------------------------------------------------
__global__ __launch_bounds__(256, 2) void gemm_kv_kernel(
    const float* __restrict__ A, const float* __restrict__ W)
{
    __shared__ float As[2][16][132];
    __shared__ float Bs[2][16][132];
    const int t = threadIdx.x;
    const int row0 = blockIdx.x * 128;
    const int col0 = blockIdx.y * 128;
    const int lr = t >> 2;
    const int lk = (t & 3) << 2;
    const int ty = t >> 4, tx = t & 15;

    ull accp[4][8];
#pragma unroll
    for (int i = 0; i < 4; i++)
#pragma unroll
        for (int j = 0; j < 8; j++) accp[i][j] = 0ull;

    int src[2];
#pragma unroll
    for (int i = 0; i < 2; i++) {
        int gr = row0 + lr + i * 64;
        if (gr < GRn) {
            int b = gr / MMn;
            int m = gr - b * MMn;
            src[i] = b * NNt + token_of(m);
        } else src[i] = -1;
    }
    const int c0 = col0 + lr, c1 = col0 + lr + 64;

    float4 va0, va1, vb0, vb1;
#define LOADG_KV(k0)                                                                 \
    va0 = (src[0] >= 0) ? *(const float4*)(A + (size_t)src[0] * CC + (k0) + lk)      \
                        : make_float4(0.f, 0.f, 0.f, 0.f);                           \
    va1 = (src[1] >= 0) ? *(const float4*)(A + (size_t)src[1] * CC + (k0) + lk)      \
                        : make_float4(0.f, 0.f, 0.f, 0.f);                           \
    vb0 = *(const float4*)(W + (size_t)c0 * CC + (k0) + lk);                         \
    vb1 = *(const float4*)(W + (size_t)c1 * CC + (k0) + lk);

    LOADG_KV(0);
    STS_TILE(0);
    __syncthreads();

    int cur = 0;
    for (int k0 = 0; k0 < CC; k0 += 16) {
        if (k0 + 16 < CC) { LOADG_KV(k0 + 16); }
        mma_slab(As[cur], Bs[cur], ty, tx, accp);
        if (k0 + 16 < CC) {
            STS_TILE(cur ^ 1);
            __syncthreads();
            cur ^= 1;
        }
    }
#undef LOADG_KV

#pragma unroll
    for (int ip = 0; ip < 4; ip++) {
        float2 e[8];
#pragma unroll
        for (int j = 0; j < 8; j++) e[j] = unpack2(accp[ip][j]);
#pragma unroll
        for (int s = 0; s < 2; s++) {
            int gr = row0 + ty * 8 + 2 * ip + s;
            if (gr >= GRn) continue;
            int b = gr / MMn;
            int m = gr - b * MMn;
#pragma unroll
            for (int j = 0; j < 8; j++) {
                int c = col0 + tx * 8 + j;
                float val = s ? e[j].y : e[j].x;
                if (c < 768) {
                    int h = c >> 6, d = c & 63;
                    g_K[(((size_t)b * HHn + h) * MMn + m) * HDn + d] = val;
                } else {
                    int c2 = c - 768;
                    int h = c2 >> 6, d = c2 & 63;
                    g_V[(((size_t)b * HHn + h) * MMn + m) * HDn + d] = val;
                }
            }
        }
    }
}

// ---------------------------------------------------------------------------
// Attention v3: each thread-pair handles TWO adjacent queries; a thread owns
// 32 of 64 head-dims for both. K/V registers are reused across the two
// queries (2x arithmetic intensity vs v2). One shfl.xor(1) per (query, m)
// completes the 64-dim dot. No max tracking (logits bounded, |s|<~20).
// Block = 256 threads = 128 pairs = 256 queries. Grid = (96 bh, 7 q-tiles).
// ---------------------------------------------------------------------------
__global__ __launch_bounds__(256, 1) void attn_kernel()
{
    extern __shared__ float sm[];
    float* Ks = sm;
    float* Vs = sm + MMn * HDn;
    const int bh = blockIdx.x;                   // 0..95 = b*12+h
    const float* Kg = g_K + (size_t)bh * MMn * HDn;
    const float* Vg = g_V + (size_t)bh * MMn * HDn;

    for (int i = threadIdx.x; i < MMn * HDn / 4; i += 256) {
        ((float4*)Ks)[i] = ((const float4*)Kg)[i];
        ((float4*)Vs)[i] = ((const float4*)Vg)[i];
    }
    __syncthreads();

    const int half = threadIdx.x & 1;
    const int pair = threadIdx.x >> 1;           // 0..127
    const int n0 = blockIdx.y * 256 + pair * 2;
    const int n1 = n0 + 1;
    const bool ok0 = (n0 < NNt), ok1 = (n1 < NNt);
    const int q0r = ok0 ? n0 : (NNt - 1);
    const int q1r = ok1 ? n1 : (NNt - 1);
    const int b = bh / HHn, h = bh % HHn;

    const int f0 = q0r / NO, f1 = q1r / NO;
    const int cs0 = (f0 < 4) ? (8 + 25 * f0) : (108 + 24 * (f0 - 4));
    const int ce0 = cs0 + ((f0 < 4) ? 25 : 24);
    const int cs1 = (f1 < 4) ? (8 + 25 * f1) : (108 + 24 * (f1 - 4));
    const int ce1 = cs1 + ((f1 < 4) ? 25 : 24);

    // my 32 head-dims of both queries, packed as f32x2 pairs of dims
    ull qp0[16], qp1[16];
    {
        const ulonglong2* a = (const ulonglong2*)(g_Q + (size_t)(b * NNt + q0r) * CC
                                                  + h * HDn + half * 32);
        const ulonglong2* c = (const ulonglong2*)(g_Q + (size_t)(b * NNt + q1r) * CC
                                                  + h * HDn + half * 32);
#pragma unroll
        for (int i = 0; i < 8; i++) {
            ulonglong2 v = a[i]; qp0[2 * i] = v.x; qp0[2 * i + 1] = v.y;
            ulonglong2 w = c[i]; qp1[2 * i] = w.x; qp1[2 * i + 1] = w.y;
        }
    }
    ull accp0[16], accp1[16];
#pragma unroll
    for (int i = 0; i < 16; i++) { accp0[i] = 0ull; accp1[i] = 0ull; }
    float den0 = 0.f, den1 = 0.f;

#pragma unroll 2
    for (int m = 0; m < MMn; m++) {
        const ulonglong2* k2 = (const ulonglong2*)(Ks + m * HDn + half * 32);
        ull sa0 = 0ull, sa1 = 0ull, sb0 = 0ull, sb1 = 0ull;
#pragma unroll
        for (int i = 0; i < 8; i++) {
            ulonglong2 kv = k2[i];
            FMA2(sa0, qp0[2 * i], kv.x);
            FMA2(sa1, qp0[2 * i + 1], kv.y);
            FMA2(sb0, qp1[2 * i], kv.x);
            FMA2(sb1, qp1[2 * i + 1], kv.y);
        }
        ull sc0, sc1;
        ADD2(sc0, sa0, sa1);
        ADD2(sc1, sb0, sb1);
        float2 e0 = unpack2(sc0), e1 = unpack2(sc1);
        float sh0 = e0.x + e0.y;
        float sh1 = e1.x + e1.y;
        float d0 = sh0 + __shfl_xor_sync(0xffffffffu, sh0, 1);
        float d1 = sh1 + __shfl_xor_sync(0xffffffffu, sh1, 1);

        // (q.k * 0.125) * mask{1.0, 0.8}
        float mult0 = (m < 8 || (m >= cs0 && m < ce0)) ? 0.125f : 0.1f;
        float mult1 = (m < 8 || (m >= cs1 && m < ce1)) ? 0.125f : 0.1f;
        float p0 = __expf(d0 * mult0);
        float p1 = __expf(d1 * mult1);
        den0 += p0; den1 += p1;
        ull pd0 = pack2_dup(p0), pd1 = pack2_dup(p1);

        const ulonglong2* v2 = (const ulonglong2*)(Vs + m * HDn + half * 32);
#pragma unroll
        for (int i = 0; i < 8; i++) {
            ulonglong2 vv = v2[i];
            FMA2(accp0[2 * i], pd0, vv.x);
            FMA2(accp0[2 * i + 1], pd0, vv.y);
            FMA2(accp1[2 * i], pd1, vv.x);
            FMA2(accp1[2 * i + 1], pd1, vv.y);
        }
    }

    if (ok0) {
        float inv = 1.f / den0;
        float* o = g_O + (size_t)(b * NNt + n0) * CC + h * HDn + half * 32;
#pragma unroll
        for (int i = 0; i < 8; i++) {
            float2 e0 = unpack2(accp0[2 * i]);
            float2 e1 = unpack2(accp0[2 * i + 1]);
            ((float4*)o)[i] = make_float4(e0.x * inv, e0.y * inv, e1.x * inv, e1.y * inv);
        }
    }
    if (ok1) {
        float inv = 1.f / den1;
        float* o = g_O + (size_t)(b * NNt + n1) * CC + h * HDn + half * 32;
#pragma unroll
        for (int i = 0; i < 8; i++) {
            float2 e0 = unpack2(accp1[2 * i]);
            float2 e1 = unpack2(accp1[2 * i + 1]);
            ((float4*)o)[i] = make_float4(e0.x * inv, e0.y * inv, e1.x * inv, e1.y * inv);
        }
    }
}

// ---------------------------------------------------------------------------
// GEMM 3: out = g_O @ proj_w^T + proj_b   (12608 x 768, K=768)
// ---------------------------------------------------------------------------
__global__ __launch_bounds__(256, 2) void gemm_proj_kernel(
    const float* __restrict__ W, const float* __restrict__ bias,
    float* __restrict__ Cout)
{
    __shared__ float As[2][16][132];
    __shared__ float Bs[2][16][132];
    const int t = threadIdx.x;
    const int row0 = blockIdx.x * 128;
    const int col0 = blockIdx.y * 128;
    const int lr = t >> 2;
    const int lk = (t & 3) << 2;
    const int ty = t >> 4, tx = t & 15;
    const float* A = g_O;

    ull accp[4][8];
#pragma unroll
    for (int i = 0; i < 4; i++)
#pragma unroll
        for (int j = 0; j < 8; j++) accp[i][j] = 0ull;

    const int r0 = row0 + lr, r1 = row0 + lr + 64;
    const int c0 = col0 + lr, c1 = col0 + lr + 64;

    float4 va0, va1, vb0, vb1;
#define LOADG_P(k0)                                                                  \
    va0 = (r0 < ROWSn) ? *(const float4*)(A + (size_t)r0 * CC + (k0) + lk)           \
                       : make_float4(0.f, 0.f, 0.f, 0.f);                            \
    va1 = (r1 < ROWSn) ? *(const float4*)(A + (size_t)r1 * CC + (k0) + lk)           \
                       : make_float4(0.f, 0.f, 0.f, 0.f);                            \
    vb0 = *(const float4*)(W + (size_t)c0 * CC + (k0) + lk);                         \
    vb1 = *(const float4*)(W + (size_t)c1 * CC + (k0) + lk);

    LOADG_P(0);
    STS_TILE(0);
    __syncthreads();

    int cur = 0;
    for (int k0 = 0; k0 < CC; k0 += 16) {
        if (k0 + 16 < CC) { LOADG_P(k0 + 16); }
        mma_slab(As[cur], Bs[cur], ty, tx, accp);
        if (k0 + 16 < CC) {
            STS_TILE(cur ^ 1);
            __syncthreads();
            cur ^= 1;
        }
    }
#undef LOADG_P

    float bv[8];
#pragma unroll
    for (int j = 0; j < 8; j++) bv[j] = bias[col0 + tx * 8 + j];

#pragma unroll
    for (int ip = 0; ip < 4; ip++) {
        float2 e[8];
#pragma unroll
        for (int j = 0; j < 8; j++) e[j] = unpack2(accp[ip][j]);
        int r = row0 + ty * 8 + 2 * ip;
        if (r < ROWSn) {
            float* dst = Cout + (size_t)r * CC + col0 + tx * 8;
            *(float4*)(dst)     = make_float4(e[0].x + bv[0], e[1].x + bv[1],
                                              e[2].x + bv[2], e[3].x + bv[3]);
            *(float4*)(dst + 4) = make_float4(e[4].x + bv[4], e[5].x + bv[5],
                                              e[6].x + bv[6], e[7].x + bv[7]);
        }
        if (r + 1 < ROWSn) {
            float* dst = Cout + (size_t)(r + 1) * CC + col0 + tx * 8;
            *(float4*)(dst)     = make_float4(e[0].y + bv[0], e[1].y + bv[1],
                                              e[2].y + bv[2], e[3].y + bv[3]);
            *(float4*)(dst + 4) = make_float4(e[4].y + bv[4], e[5].y + bv[5],
                                              e[6].y + bv[6], e[7].y + bv[7]);
        }
    }
}

// ---------------------------------------------------------------------------
extern "C" void kernel_launch(void* const* d_in, const int* in_sizes, int n_in,
                              void* d_out, int out_size)
{
    const float* x      = (const float*)d_in[0];
    const float* qkv_w  = (const float*)d_in[1];
    const float* proj_w = (const float*)d_in[2];
    const float* proj_b = (const float*)d_in[3];
    float* out = (float*)d_out;

    cudaFuncSetAttribute(attn_kernel,
                         cudaFuncAttributeMaxDynamicSharedMemorySize, SMEM_ATTN);

    dim3 blk(256);
    // Q projection: 12608 x 768
    gemm_q_kernel<<<dim3(99, 6), blk>>>(x, qkv_w);
    // gathered K/V projection: 1632 x 1536 (uses qkv_w rows 768..2303)
    gemm_kv_kernel<<<dim3(13, 12), blk>>>(x, qkv_w + 768 * CC);
    // attention: 96 (b,h) blocks x 7 query tiles of 256
    attn_kernel<<<dim3(96, 7), blk, SMEM_ATTN>>>();
    // output projection + bias: 12608 x 768
    gemm_proj_kernel<<<dim3(99, 6), blk>>>(proj_w, proj_b, out);
}

// round 8
// speedup vs baseline: 1.8759x; 1.5890x over previous
#include <cuda_runtime.h>
#include <cuda_bf16.h>

// Problem constants
#define CC    768        // channels
#define NO    197        // tokens per frame (N_origin)
#define FRn   8          // FRAMES
#define BBn   8          // batch after frame-fold (64/8)
#define NNt   1576       // FRn*NO
#define HHn   12         // heads
#define HDn   64         // head dim
#define MMn   204        // gathered tokens (8 cls + 196)
#define ROWSn 12608      // BBn*NNt (= 64*197)
#define GRn   1632       // BBn*MMn

#define SMEM_ATTN (2 * MMn * HDn * 4)   // K + V tiles in fp32 = 104448 B

// HMMA GEMM smem layout (bf16 elements)
#define KPAD    40                       // padded K per smem row (80B stride)
#define TILE_E  (128 * KPAD)             // 5120 elems per tile
#define OFF_AHI 0
#define OFF_ALO TILE_E
#define OFF_WHI (2 * TILE_E)
#define OFF_WLO (3 * TILE_E)
#define STAGE_E (4 * TILE_E)             // 20480 elems per stage
#define SMEM_GEMM (2 * STAGE_E * 2)      // 81920 bytes (double buffered)

typedef unsigned long long ull;
typedef __nv_bfloat16 bf16;

// Scratch (device globals; no allocation allowed)
__device__ float g_Q[ROWSn * CC];                 // Q projection, token-major
__device__ float g_K[BBn * HHn * MMn * HDn];      // gathered K, [b][h][m][d]
__device__ float g_V[BBn * HHn * MMn * HDn];      // gathered V, [b][h][m][d]
__device__ float g_O[ROWSn * CC];                 // attention output, token-major

// hi/lo split bf16 copies
__device__ bf16 g_xhi[ROWSn * CC];
__device__ bf16 g_xlo[ROWSn * CC];
__device__ bf16 g_wqhi[3 * CC * CC];
__device__ bf16 g_wqlo[3 * CC * CC];
__device__ bf16 g_wphi[CC * CC];
__device__ bf16 g_wplo[CC * CC];
__device__ bf16 g_ohi[ROWSn * CC];
__device__ bf16 g_olo[ROWSn * CC];

// ---------------------------------------------------------------------------
// Packed f32x2 helpers (Blackwell sm_100+) - used by attention
// ---------------------------------------------------------------------------
#define FMA2(c, a, b) asm("fma.rn.f32x2 %0, %1, %2, %0;" : "+l"(c) : "l"(a), "l"(b))
#define ADD2(d, a, b) asm("add.rn.f32x2 %0, %1, %2;" : "=l"(d) : "l"(a), "l"(b))

__device__ __forceinline__ ull pack2_dup(float v) {
    ull r; unsigned u = __float_as_uint(v);
    asm("mov.b64 %0, {%1, %1};" : "=l"(r) : "r"(u));
    return r;
}
__device__ __forceinline__ float2 unpack2(ull v) {
    float2 f;
    asm("mov.b64 {%0, %1}, %2;" : "=f"(f.x), "=f"(f.y) : "l"(v));
    return f;
}

// token index of gathered column m (matches _build_indices_mask)
__device__ __forceinline__ int token_of(int m) {
    if (m < 8) return m * NO;            // cls tokens
    int r = m - 8;
    int f, j;
    if (r < 100) { f = r / 25; j = r - f * 25; }     // frames 0..3, len 25
    else { r -= 100; f = 4 + r / 24; j = r % 24; }   // frames 4..7, len 24
    return f * NO + 1 + f + 8 * j;
}

// ---------------------------------------------------------------------------
// fp32 -> (bf16 hi, bf16 lo) split conversion, 4 elems/thread
// ---------------------------------------------------------------------------
__global__ __launch_bounds__(256) void cvt_hilo(
    const float* __restrict__ s, bf16* __restrict__ h, bf16* __restrict__ l, int n4)
{
    int i = blockIdx.x * 256 + threadIdx.x;
    if (i >= n4) return;
    float4 v = ((const float4*)s)[i];
    bf16 h0 = __float2bfloat16(v.x), h1 = __float2bfloat16(v.y);
    bf16 h2 = __float2bfloat16(v.z), h3 = __float2bfloat16(v.w);
    float r0 = v.x - __bfloat162float(h0), r1 = v.y - __bfloat162float(h1);
    float r2 = v.z - __bfloat162float(h2), r3 = v.w - __bfloat162float(h3);
    __nv_bfloat162* hp = (__nv_bfloat162*)h;
    __nv_bfloat162* lp = (__nv_bfloat162*)l;
    hp[2 * i]     = __nv_bfloat162(h0, h1);
    hp[2 * i + 1] = __nv_bfloat162(h2, h3);
    lp[2 * i]     = __floats2bfloat162_rn(r0, r1);
    lp[2 * i + 1] = __floats2bfloat162_rn(r2, r3);
}

// ---------------------------------------------------------------------------
// HMMA primitives
// ---------------------------------------------------------------------------
__device__ __forceinline__ unsigned smem_u32(const void* p) {
    return (unsigned)__cvta_generic_to_shared(p);
}
__device__ __forceinline__ void ldsm4(unsigned addr, unsigned& r0, unsigned& r1,
                                      unsigned& r2, unsigned& r3) {
    asm volatile("ldmatrix.sync.aligned.m8n8.x4.shared.b16 {%0,%1,%2,%3}, [%4];"
                 : "=r"(r0), "=r"(r1), "=r"(r2), "=r"(r3) : "r"(addr));
}
__device__ __forceinline__ void mma16816(float* d, const unsigned* a, const unsigned* b) {
    asm volatile(
        "mma.sync.aligned.m16n8k16.row.col.f32.bf16.bf16.f32 "
        "{%0,%1,%2,%3}, {%4,%5,%6,%7}, {%8,%9}, {%0,%1,%2,%3};"
        : "+f"(d[0]), "+f"(d[1]), "+f"(d[2]), "+f"(d[3])
        : "r"(a[0]), "r"(a[1]), "r"(a[2]), "r"(a[3]), "r"(b[0]), "r"(b[1]));
}

// global->smem slab load: A (hi,lo) rows pA0/pA1 (nullptr => zero), W cols cW0/cW1
__device__ __forceinline__ void load_slab(
    bf16* s, const bf16* pA0h, const bf16* pA0l, const bf16* pA1h, const bf16* pA1l,
    const bf16* pW0h, const bf16* pW0l, const bf16* pW1h, const bf16* pW1l,
    int k0, int t)
{
    const int row = t >> 2;
    const int sub = (t & 3) * 8;       // bf16 elems
    const int so0 = row * KPAD + sub;
    const int so1 = (row + 64) * KPAD + sub;
    const uint4 z = make_uint4(0, 0, 0, 0);
    uint4 ah0 = pA0h ? *(const uint4*)(pA0h + k0 + sub) : z;
    uint4 ah1 = pA1h ? *(const uint4*)(pA1h + k0 + sub) : z;
    uint4 al0 = pA0l ? *(const uint4*)(pA0l + k0 + sub) : z;
    uint4 al1 = pA1l ? *(const uint4*)(pA1l + k0 + sub) : z;
    uint4 wh0 = *(const uint4*)(pW0h + k0 + sub);
    uint4 wh1 = *(const uint4*)(pW1h + k0 + sub);
    uint4 wl0 = *(const uint4*)(pW0l + k0 + sub);
    uint4 wl1 = *(const uint4*)(pW1l + k0 + sub);
    *(uint4*)(s + OFF_AHI + so0) = ah0;  *(uint4*)(s + OFF_AHI + so1) = ah1;
    *(uint4*)(s + OFF_ALO + so0) = al0;  *(uint4*)(s + OFF_ALO + so1) = al1;
    *(uint4*)(s + OFF_WHI + so0) = wh0;  *(uint4*)(s + OFF_WHI + so1) = wh1;
    *(uint4*)(s + OFF_WLO + so0) = wl0;  *(uint4*)(s + OFF_WLO + so1) = wl1;
}

// compute one 32-wide K slab: warp tile 32x64, 3-way split-bf16 accumulate
__device__ __forceinline__ void hmma_slab(const bf16* s, int wm, int wn, int lane,
                                          float acc[2][8][4])
{
#pragma unroll
    for (int ks = 0; ks < 2; ks++) {
        const int arow = wm * 32 + (lane & 15);
        const int acol = ks * 16 + (lane >> 4) * 8;
        unsigned ahi[2][4], alo[2][4];
#pragma unroll
        for (int mt = 0; mt < 2; mt++) {
            ldsm4(smem_u32(s + OFF_AHI + (arow + mt * 16) * KPAD + acol),
                  ahi[mt][0], ahi[mt][1], ahi[mt][2], ahi[mt][3]);
            ldsm4(smem_u32(s + OFF_ALO + (arow + mt * 16) * KPAD + acol),
                  alo[mt][0], alo[mt][1], alo[mt][2], alo[mt][3]);
        }
        const int brow = wn * 64 + (lane & 7) + ((lane >> 4) << 3);
        const int bcol = ks * 16 + ((lane >> 3) & 1) * 8;
        unsigned bhi[8][2], blo[8][2];
#pragma unroll
        for (int np = 0; np < 4; np++) {
            unsigned r0, r1, r2, r3;
            ldsm4(smem_u32(s + OFF_WHI + (brow + np * 16) * KPAD + bcol), r0, r1, r2, r3);
            bhi[2 * np][0] = r0; bhi[2 * np][1] = r1;
            bhi[2 * np + 1][0] = r2; bhi[2 * np + 1][1] = r3;
            ldsm4(smem_u32(s + OFF_WLO + (brow + np * 16) * KPAD + bcol), r0, r1, r2, r3);
            blo[2 * np][0] = r0; blo[2 * np][1] = r1;
            blo[2 * np + 1][0] = r2; blo[2 * np + 1][1] = r3;
        }
#pragma unroll
        for (int mt = 0; mt < 2; mt++)
#pragma unroll
            for (int nf = 0; nf < 8; nf++) {
                mma16816(acc[mt][nf], ahi[mt], bhi[nf]);
                mma16816(acc[mt][nf], ahi[mt], blo[nf]);
                mma16816(acc[mt][nf], alo[mt], bhi[nf]);
            }
    }
}

// full mainloop: fills acc for this block's 128x128 tile
__device__ __forceinline__ void hmma_mainloop(
    const bf16* pA0h, const bf16* pA0l, const bf16* pA1h, const bf16* pA1l,
    const bf16* pW0h, const bf16* pW0l, const bf16* pW1h, const bf16* pW1l,
    float acc[2][8][4])
{
    extern __shared__ bf16 sbuf[];
    const int t = threadIdx.x;
    const int wid = t >> 5, lane = t & 31;
    const int wm = wid & 3, wn = wid >> 2;

#pragma unroll
    for (int i = 0; i < 2; i++)
#pragma unroll
        for (int j = 0; j < 8; j++)
#pragma unroll
            for (int v = 0; v < 4; v++) acc[i][j][v] = 0.f;

    load_slab(sbuf, pA0h, pA0l, pA1h, pA1l, pW0h, pW0l, pW1h, pW1l, 0, t);
    __syncthreads();
    for (int sl = 0; sl < 24; sl++) {
        if (sl + 1 < 24)
            load_slab(sbuf + ((sl + 1) & 1) * STAGE_E,
                      pA0h, pA0l, pA1h, pA1l, pW0h, pW0l, pW1h, pW1l,
                      (sl + 1) * 32, t);
        hmma_slab(sbuf + (sl & 1) * STAGE_E, wm, wn, lane, acc);
        __syncthreads();
    }
}

// ---------------------------------------------------------------------------
// GEMM 1: Q = X @ Wq^T -> g_Q fp32   (12608 x 768, K=768), grid (99, 6)
// ---------------------------------------------------------------------------
__global__ __launch_bounds__(256) void gemm_q_hmma()
{
    const int t = threadIdx.x;
    const int row0 = blockIdx.x * 128, col0 = blockIdx.y * 128;
    const int wid = t >> 5, lane = t & 31;
    const int wm = wid & 3, wn = wid >> 2;

    const int rA0 = row0 + (t >> 2), rA1 = rA0 + 64;
    const int cW0 = col0 + (t >> 2), cW1 = cW0 + 64;
    const bf16* pA0h = (rA0 < ROWSn) ? g_xhi + (size_t)rA0 * CC : nullptr;
    const bf16* pA0l = (rA0 < ROWSn) ? g_xlo + (size_t)rA0 * CC : nullptr;
    const bf16* pA1h = (rA1 < ROWSn) ? g_xhi + (size_t)rA1 * CC : nullptr;
    const bf16* pA1l = (rA1 < ROWSn) ? g_xlo + (size_t)rA1 * CC : nullptr;

    float acc[2][8][4];
    hmma_mainloop(pA0h, pA0l, pA1h, pA1l,
                  g_wqhi + (size_t)cW0 * CC, g_wqlo + (size_t)cW0 * CC,
                  g_wqhi + (size_t)cW1 * CC, g_wqlo + (size_t)cW1 * CC, acc);

    const int quad = lane >> 2, qp = lane & 3;
#pragma unroll
    for (int mt = 0; mt < 2; mt++)
#pragma unroll
        for (int nf = 0; nf < 8; nf++) {
            int r = row0 + wm * 32 + mt * 16 + quad;
            int c = col0 + wn * 64 + nf * 8 + qp * 2;
            if (r < ROWSn)
                *(float2*)&g_Q[(size_t)r * CC + c] = make_float2(acc[mt][nf][0], acc[mt][nf][1]);
            if (r + 8 < ROWSn)
                *(float2*)&g_Q[(size_t)(r + 8) * CC + c] = make_float2(acc[mt][nf][2], acc[mt][nf][3]);
        }
}

// ---------------------------------------------------------------------------
// GEMM 2: gathered K/V projection (1632 x 1536, K=768), grid (13, 12)
// ---------------------------------------------------------------------------
__global__ __launch_bounds__(256) void gemm_kv_hmma()
{
    const int t = threadIdx.x;
    const int row0 = blockIdx.x * 128, col0 = blockIdx.y * 128;
    const int wid = t >> 5, lane = t & 31;
    const int wm = wid & 3, wn = wid >> 2;

    const bf16* pA[2][2] = {{nullptr, nullptr}, {nullptr, nullptr}};
#pragma unroll
    for (int i = 0; i < 2; i++) {
        int gr = row0 + (t >> 2) + i * 64;
        if (gr < GRn) {
            int b = gr / MMn, m = gr - b * MMn;
            size_t src = (size_t)(b * NNt + token_of(m)) * CC;
            pA[i][0] = g_xhi + src; pA[i][1] = g_xlo + src;
        }
    }
    const int cW0 = col0 + (t >> 2), cW1 = cW0 + 64;
    const bf16* wbase_h = g_wqhi + (size_t)768 * CC;   // k/v weight rows
    const bf16* wbase_l = g_wqlo + (size_t)768 * CC;

    float acc[2][8][4];
    hmma_mainloop(pA[0][0], pA[0][1], pA[1][0], pA[1][1],
                  wbase_h + (size_t)cW0 * CC, wbase_l + (size_t)cW0 * CC,
                  wbase_h + (size_t)cW1 * CC, wbase_l + (size_t)cW1 * CC, acc);

    const int quad = lane >> 2, qp = lane & 3;
#pragma unroll
    for (int mt = 0; mt < 2; mt++)
#pragma unroll
        for (int nf = 0; nf < 8; nf++) {
#pragma unroll
            for (int up = 0; up < 2; up++) {
                int gr = row0 + wm * 32 + mt * 16 + quad + up * 8;
                if (gr >= GRn) continue;
                int b = gr / MMn, m = gr - b * MMn;
                int c = col0 + wn * 64 + nf * 8 + qp * 2;
                float2 val = make_float2(acc[mt][nf][2 * up], acc[mt][nf][2 * up + 1]);
                if (c < 768) {
                    int h = c >> 6, d = c & 63;
                    *(float2*)&g_K[(((size_t)b * HHn + h) * MMn + m) * HDn + d] = val;
                } else {
                    int c2 = c - 768;
                    int h = c2 >> 6, d = c2 & 63;
                    *(float2*)&g_V[(((size_t)b * HHn + h) * MMn + m) * HDn + d] = val;
                }
            }
        }
}

// ---------------------------------------------------------------------------
// GEMM 3: out = O @ proj_w^T + proj_b   (12608 x 768, K=768), grid (99, 6)
// ---------------------------------------------------------------------------
__global__ __launch_bounds__(256) void gemm_proj_hmma(
    const float* __restrict__ bias, float* __restrict__ Cout)
{
    const int t = threadIdx.x;
    const int row0 = blockIdx.x * 128, col0 = blockIdx.y * 128;
    const int wid = t >> 5, lane = t & 31;
    const int wm = wid & 3, wn = wid >> 2;

    const int rA0 = row0 + (t >> 2), rA1 = rA0 + 64;
    const int cW0 = col0 + (t >> 2), cW1 = cW0 + 64;
    const bf16* pA0h = (rA0 < ROWSn) ? g_ohi + (size_t)rA0 * CC : nullptr;
    const bf16* pA0l = (rA0 < ROWSn) ? g_olo + (size_t)rA0 * CC : nullptr;
    const bf16* pA1h = (rA1 < ROWSn) ? g_ohi + (size_t)rA1 * CC : nullptr;
    const bf16* pA1l = (rA1 < ROWSn) ? g_olo + (size_t)rA1 * CC : nullptr;

    float acc[2][8][4];
    hmma_mainloop(pA0h, pA0l, pA1h, pA1l,
                  g_wphi + (size_t)cW0 * CC, g_wplo + (size_t)cW0 * CC,
                  g_wphi + (size_t)cW1 * CC, g_wplo + (size_t)cW1 * CC, acc);

    const int quad = lane >> 2, qp = lane & 3;
#pragma unroll
    for (int nf = 0; nf < 8; nf++) {
        int c = col0 + wn * 64 + nf * 8 + qp * 2;
        float2 bv = *(const float2*)&bias[c];
#pragma unroll
        for (int mt = 0; mt < 2; mt++) {
            int r = row0 + wm * 32 + mt * 16 + quad;
            if (r < ROWSn)
                *(float2*)&Cout[(size_t)r * CC + c] =
                    make_float2(acc[mt][nf][0] + bv.x, acc[mt][nf][1] + bv.y);
            if (r + 8 < ROWSn)
                *(float2*)&Cout[(size_t)(r + 8) * CC + c] =
                    make_float2(acc[mt][nf][2] + bv.x, acc[mt][nf][3] + bv.y);
        }
    }
}

// ---------------------------------------------------------------------------
// Attention (unchanged from R6): thread-pair handles 2 queries, 32 dims each.
// ---------------------------------------------------------------------------
__global__ __launch_bounds__(256, 1) void attn_kernel()
{
    extern __shared__ float sm[];
    float* Ks = sm;
    float* Vs = sm + MMn * HDn;
    const int bh = blockIdx.x;
    const float* Kg = g_K + (size_t)bh * MMn * HDn;
    const float* Vg = g_V + (size_t)bh * MMn * HDn;

    for (int i = threadIdx.x; i < MMn * HDn / 4; i += 256) {
        ((float4*)Ks)[i] = ((const float4*)Kg)[i];
        ((float4*)Vs)[i] = ((const float4*)Vg)[i];
    }
    __syncthreads();

    const int half = threadIdx.x & 1;
    const int pair = threadIdx.x >> 1;
    const int n0 = blockIdx.y * 256 + pair * 2;
    const int n1 = n0 + 1;
    const bool ok0 = (n0 < NNt), ok1 = (n1 < NNt);
    const int q0r = ok0 ? n0 : (NNt - 1);
    const int q1r = ok1 ? n1 : (NNt - 1);
    const int b = bh / HHn, h = bh % HHn;

    const int f0 = q0r / NO, f1 = q1r / NO;
    const int cs0 = (f0 < 4) ? (8 + 25 * f0) : (108 + 24 * (f0 - 4));
    const int ce0 = cs0 + ((f0 < 4) ? 25 : 24);
    const int cs1 = (f1 < 4) ? (8 + 25 * f1) : (108 + 24 * (f1 - 4));
    const int ce1 = cs1 + ((f1 < 4) ? 25 : 24);

    ull qp0[16], qp1[16];
    {
        const ulonglong2* a = (const ulonglong2*)(g_Q + (size_t)(b * NNt + q0r) * CC
                                                  + h * HDn + half * 32);
        const ulonglong2* c = (const ulonglong2*)(g_Q + (size_t)(b * NNt + q1r) * CC
                                                  + h * HDn + half * 32);
#pragma unroll
        for (int i = 0; i < 8; i++) {
            ulonglong2 v = a[i]; qp0[2 * i] = v.x; qp0[2 * i + 1] = v.y;
            ulonglong2 w = c[i]; qp1[2 * i] = w.x; qp1[2 * i + 1] = w.y;
        }
    }
    ull accp0[16], accp1[16];
#pragma unroll
    for (int i = 0; i < 16; i++) { accp0[i] = 0ull; accp1[i] = 0ull; }
    float den0 = 0.f, den1 = 0.f;

#pragma unroll 2
    for (int m = 0; m < MMn; m++) {
        const ulonglong2* k2 = (const ulonglong2*)(Ks + m * HDn + half * 32);
        ull sa0 = 0ull, sa1 = 0ull, sb0 = 0ull, sb1 = 0ull;
#pragma unroll
        for (int i = 0; i < 8; i++) {
            ulonglong2 kv = k2[i];
            FMA2(sa0, qp0[2 * i], kv.x);
            FMA2(sa1, qp0[2 * i + 1], kv.y);
            FMA2(sb0, qp1[2 * i], kv.x);
            FMA2(sb1, qp1[2 * i + 1], kv.y);
        }
        ull sc0, sc1;
        ADD2(sc0, sa0, sa1);
        ADD2(sc1, sb0, sb1);
        float2 e0 = unpack2(sc0), e1 = unpack2(sc1);
        float sh0 = e0.x + e0.y;
        float sh1 = e1.x + e1.y;
        float d0 = sh0 + __shfl_xor_sync(0xffffffffu, sh0, 1);
        float d1 = sh1 + __shfl_xor_sync(0xffffffffu, sh1, 1);

        float mult0 = (m < 8 || (m >= cs0 && m < ce0)) ? 0.125f : 0.1f;
        float mult1 = (m < 8 || (m >= cs1 && m < ce1)) ? 0.125f : 0.1f;
        float p0 = __expf(d0 * mult0);
        float p1 = __expf(d1 * mult1);
        den0 += p0; den1 += p1;
        ull pd0 = pack2_dup(p0), pd1 = pack2_dup(p1);

        const ulonglong2* v2 = (const ulonglong2*)(Vs + m * HDn + half * 32);
#pragma unroll
        for (int i = 0; i < 8; i++) {
            ulonglong2 vv = v2[i];
            FMA2(accp0[2 * i], pd0, vv.x);
            FMA2(accp0[2 * i + 1], pd0, vv.y);
            FMA2(accp1[2 * i], pd1, vv.x);
            FMA2(accp1[2 * i + 1], pd1, vv.y);
        }
    }

    if (ok0) {
        float inv = 1.f / den0;
        float* o = g_O + (size_t)(b * NNt + n0) * CC + h * HDn + half * 32;
#pragma unroll
        for (int i = 0; i < 8; i++) {
            float2 e0 = unpack2(accp0[2 * i]);
            float2 e1 = unpack2(accp0[2 * i + 1]);
            ((float4*)o)[i] = make_float4(e0.x * inv, e0.y * inv, e1.x * inv, e1.y * inv);
        }
    }
    if (ok1) {
        float inv = 1.f / den1;
        float* o = g_O + (size_t)(b * NNt + n1) * CC + h * HDn + half * 32;
#pragma unroll
        for (int i = 0; i < 8; i++) {
            float2 e0 = unpack2(accp1[2 * i]);
            float2 e1 = unpack2(accp1[2 * i + 1]);
            ((float4*)o)[i] = make_float4(e0.x * inv, e0.y * inv, e1.x * inv, e1.y * inv);
        }
    }
}

// ---------------------------------------------------------------------------
extern "C" void kernel_launch(void* const* d_in, const int* in_sizes, int n_in,
                              void* d_out, int out_size)
{
    const float* x      = (const float*)d_in[0];
    const float* qkv_w  = (const float*)d_in[1];
    const float* proj_w = (const float*)d_in[2];
    const float* proj_b = (const float*)d_in[3];
    float* out = (float*)d_out;

    cudaFuncSetAttribute(attn_kernel,
                         cudaFuncAttributeMaxDynamicSharedMemorySize, SMEM_ATTN);
    cudaFuncSetAttribute(gemm_q_hmma,
                         cudaFuncAttributeMaxDynamicSharedMemorySize, SMEM_GEMM);
    cudaFuncSetAttribute(gemm_kv_hmma,
                         cudaFuncAttributeMaxDynamicSharedMemorySize, SMEM_GEMM);
    cudaFuncSetAttribute(gemm_proj_hmma,
                         cudaFuncAttributeMaxDynamicSharedMemorySize, SMEM_GEMM);

    bf16 *xhi, *xlo, *wqhi, *wqlo, *wphi, *wplo, *ohi, *olo;
    float* oBuf;
    cudaGetSymbolAddress((void**)&xhi, g_xhi);
    cudaGetSymbolAddress((void**)&xlo, g_xlo);
    cudaGetSymbolAddress((void**)&wqhi, g_wqhi);
    cudaGetSymbolAddress((void**)&wqlo, g_wqlo);
    cudaGetSymbolAddress((void**)&wphi, g_wphi);
    cudaGetSymbolAddress((void**)&wplo, g_wplo);
    cudaGetSymbolAddress((void**)&ohi, g_ohi);
    cudaGetSymbolAddress((void**)&olo, g_olo);
    cudaGetSymbolAddress((void**)&oBuf, g_O);

    dim3 blk(256);
    // hi/lo conversions of inputs
    int n4x = ROWSn * CC / 4;
    int n4q = 3 * CC * CC / 4;
    int n4p = CC * CC / 4;
    cvt_hilo<<<(n4x + 255) / 256, blk>>>(x, xhi, xlo, n4x);
    cvt_hilo<<<(n4q + 255) / 256, blk>>>(qkv_w, wqhi, wqlo, n4q);
    cvt_hilo<<<(n4p + 255) / 256, blk>>>(proj_w, wphi, wplo, n4p);

    // Q projection: 12608 x 768
    gemm_q_hmma<<<dim3(99, 6), blk, SMEM_GEMM>>>();
    // gathered K/V projection: 1632 x 1536
    gemm_kv_hmma<<<dim3(13, 12), blk, SMEM_GEMM>>>();
    // attention: 96 (b,h) blocks x 7 query tiles of 256
    attn_kernel<<<dim3(96, 7), blk, SMEM_ATTN>>>();
    // convert attention output, then output projection + bias
    cvt_hilo<<<(n4x + 255) / 256, blk>>>(oBuf, ohi, olo, n4x);
    gemm_proj_hmma<<<dim3(99, 6), blk, SMEM_GEMM>>>(proj_b, out);
}

// round 10
// speedup vs baseline: 2.4493x; 1.3056x over previous
#include <cuda_runtime.h>
#include <cuda_bf16.h>

// Problem constants
#define CC    768        // channels
#define NO    197        // tokens per frame (N_origin)
#define FRn   8          // FRAMES
#define BBn   8          // batch after frame-fold (64/8)
#define NNt   1576       // FRn*NO
#define HHn   12         // heads
#define HDn   64         // head dim
#define MMn   204        // gathered tokens (8 cls + 196)
#define ROWSn 12608      // BBn*NNt (= 64*197)
#define GRn   1632       // BBn*MMn
#define NBH   96         // BBn*HHn

// HMMA GEMM smem layout (bf16 elements)
#define KPAD    40                       // padded K per smem row (80B stride)
#define TILE_E  (128 * KPAD)             // 5120 elems per tile
#define OFF_AHI 0
#define OFF_ALO TILE_E
#define OFF_WHI (2 * TILE_E)
#define OFF_WLO (3 * TILE_E)
#define STAGE_E (4 * TILE_E)             // 20480 elems per stage
#define SMEM_GEMM (2 * STAGE_E * 2)      // 81920 bytes (double buffered)

// Attention smem layout (bf16 element offsets)
#define KKp  208                         // padded key count (204 -> 208)
#define QKP  72                          // Q/K smem row stride (144 B)
#define VPP  216                         // Vt / P smem row stride (432 B)
#define SQHI 0                           // Q hi: 128 x 72
#define SQLO 9216
#define SKHI 18432                       // K hi: 208 x 72
#define SKLO 33408
#define SPHI 0                           // P hi: 128 x 216 (aliases Q+K)
#define SPLO 27648
#define SVHI 55296                       // Vt hi: 64 x 216
#define SVLO 69120
#define SMEM_ATT_E 82944
#define SMEM_ATT   (SMEM_ATT_E * 2)      // 165888 B

typedef unsigned long long ull;
typedef __nv_bfloat16 bf16;

// ---------------------------------------------------------------------------
// Scratch (device globals; no allocation allowed)
// ---------------------------------------------------------------------------
__device__ __align__(16) bf16 g_xhi[ROWSn * CC];
__device__ __align__(16) bf16 g_xlo[ROWSn * CC];
__device__ __align__(16) bf16 g_wqhi[3 * CC * CC];
__device__ __align__(16) bf16 g_wqlo[3 * CC * CC];
__device__ __align__(16) bf16 g_wphi[CC * CC];
__device__ __align__(16) bf16 g_wplo[CC * CC];
__device__ __align__(16) bf16 g_qhi[ROWSn * CC];      // Q projection split
__device__ __align__(16) bf16 g_qlo[ROWSn * CC];
__device__ __align__(16) bf16 g_khi[NBH * MMn * HDn]; // K [bh][m][d]
__device__ __align__(16) bf16 g_klo[NBH * MMn * HDn];
__device__ __align__(16) bf16 g_vthi[NBH * HDn * VPP]; // V^T [bh][d][m], padded
__device__ __align__(16) bf16 g_vtlo[NBH * HDn * VPP];
__device__ __align__(16) bf16 g_ohi[ROWSn * CC];      // attention out split
__device__ __align__(16) bf16 g_olo[ROWSn * CC];

// token index of gathered column m (matches _build_indices_mask)
__device__ __forceinline__ int token_of(int m) {
    if (m < 8) return m * NO;            // cls tokens
    int r = m - 8;
    int f, j;
    if (r < 100) { f = r / 25; j = r - f * 25; }     // frames 0..3, len 25
    else { r -= 100; f = 4 + r / 24; j = r % 24; }   // frames 4..7, len 24
    return f * NO + 1 + f + 8 * j;
}

// fp32 pair -> (bf16 hi pair, bf16 lo pair)
__device__ __forceinline__ void split2f(float x, float y,
                                        __nv_bfloat162& h, __nv_bfloat162& l) {
    bf16 h0 = __float2bfloat16(x), h1 = __float2bfloat16(y);
    h = __nv_bfloat162(h0, h1);
    l = __floats2bfloat162_rn(x - __bfloat162float(h0), y - __bfloat162float(h1));
}

// ---------------------------------------------------------------------------
// fp32 -> (bf16 hi, bf16 lo) split conversion, 4 elems/thread
// ---------------------------------------------------------------------------
__global__ __launch_bounds__(256) void cvt_hilo(
    const float* __restrict__ s, bf16* __restrict__ h, bf16* __restrict__ l, int n4)
{
    int i = blockIdx.x * 256 + threadIdx.x;
    if (i >= n4) return;
    float4 v = ((const float4*)s)[i];
    __nv_bfloat162 h0, l0, h1, l1;
    split2f(v.x, v.y, h0, l0);
    split2f(v.z, v.w, h1, l1);
    __nv_bfloat162* hp = (__nv_bfloat162*)h;
    __nv_bfloat162* lp = (__nv_bfloat162*)l;
    hp[2 * i] = h0; hp[2 * i + 1] = h1;
    lp[2 * i] = l0; lp[2 * i + 1] = l1;
}

// zero the pad columns (204..215) of g_vt so HMMA never sees NaN garbage
__global__ __launch_bounds__(256) void vt_zero_pad()
{
    int bh = blockIdx.x;
    for (int i = threadIdx.x; i < HDn * 12; i += 256) {
        int d = i / 12, pc = 204 + i % 12;
        size_t g = ((size_t)bh * HDn + d) * VPP + pc;
        g_vthi[g] = __float2bfloat16(0.f);
        g_vtlo[g] = __float2bfloat16(0.f);
    }
}

// ---------------------------------------------------------------------------
// HMMA primitives
// ---------------------------------------------------------------------------
__device__ __forceinline__ unsigned smem_u32(const void* p) {
    return (unsigned)__cvta_generic_to_shared(p);
}
__device__ __forceinline__ void ldsm4(unsigned addr, unsigned& r0, unsigned& r1,
                                      unsigned& r2, unsigned& r3) {
    asm volatile("ldmatrix.sync.aligned.m8n8.x4.shared.b16 {%0,%1,%2,%3}, [%4];"
                 : "=r"(r0), "=r"(r1), "=r"(r2), "=r"(r3) : "r"(addr));
}
__device__ __forceinline__ void mma16816(float* d, const unsigned* a, const unsigned* b) {
    asm volatile(
        "mma.sync.aligned.m16n8k16.row.col.f32.bf16.bf16.f32 "
        "{%0,%1,%2,%3}, {%4,%5,%6,%7}, {%8,%9}, {%0,%1,%2,%3};"
        : "+f"(d[0]), "+f"(d[1]), "+f"(d[2]), "+f"(d[3])
        : "r"(a[0]), "r"(a[1]), "r"(a[2]), "r"(a[3]), "r"(b[0]), "r"(b[1]));
}

// global->smem slab load: A (hi,lo) rows pA0/pA1 (nullptr => zero), W cols cW0/cW1
__device__ __forceinline__ void load_slab(
    bf16* s, const bf16* pA0h, const bf16* pA0l, const bf16* pA1h, const bf16* pA1l,
    const bf16* pW0h, const bf16* pW0l, const bf16* pW1h, const bf16* pW1l,
    int k0, int t)
{
    const int row = t >> 2;
    const int sub = (t & 3) * 8;       // bf16 elems
    const int so0 = row * KPAD + sub;
    const int so1 = (row + 64) * KPAD + sub;
    const uint4 z = make_uint4(0, 0, 0, 0);
    uint4 ah0 = pA0h ? *(const uint4*)(pA0h + k0 + sub) : z;
    uint4 ah1 = pA1h ? *(const uint4*)(pA1h + k0 + sub) : z;
    uint4 al0 = pA0l ? *(const uint4*)(pA0l + k0 + sub) : z;
    uint4 al1 = pA1l ? *(const uint4*)(pA1l + k0 + sub) : z;
    uint4 wh0 = *(const uint4*)(pW0h + k0 + sub);
    uint4 wh1 = *(const uint4*)(pW1h + k0 + sub);
    uint4 wl0 = *(const uint4*)(pW0l + k0 + sub);
    uint4 wl1 = *(const uint4*)(pW1l + k0 + sub);
    *(uint4*)(s + OFF_AHI + so0) = ah0;  *(uint4*)(s + OFF_AHI + so1) = ah1;
    *(uint4*)(s + OFF_ALO + so0) = al0;  *(uint4*)(s + OFF_ALO + so1) = al1;
    *(uint4*)(s + OFF_WHI + so0) = wh0;  *(uint4*)(s + OFF_WHI + so1) = wh1;
    *(uint4*)(s + OFF_WLO + so0) = wl0;  *(uint4*)(s + OFF_WLO + so1) = wl1;
}

// compute one 32-wide K slab: warp tile 32x64, 3-way split-bf16 accumulate
__device__ __forceinline__ void hmma_slab(const bf16* s, int wm, int wn, int lane,
                                          float acc[2][8][4])
{
#pragma unroll
    for (int ks = 0; ks < 2; ks++) {
        const int arow = wm * 32 + (lane & 15);
        const int acol = ks * 16 + (lane >> 4) * 8;
        unsigned ahi[2][4], alo[2][4];
#pragma unroll
        for (int mt = 0; mt < 2; mt++) {
            ldsm4(smem_u32(s + OFF_AHI + (arow + mt * 16) * KPAD + acol),
                  ahi[mt][0], ahi[mt][1], ahi[mt][2], ahi[mt][3]);
            ldsm4(smem_u32(s + OFF_ALO + (arow + mt * 16) * KPAD + acol),
                  alo[mt][0], alo[mt][1], alo[mt][2], alo[mt][3]);
        }
        const int brow = wn * 64 + (lane & 7) + ((lane >> 4) << 3);
        const int bcol = ks * 16 + ((lane >> 3) & 1) * 8;
        unsigned bhi[8][2], blo[8][2];
#pragma unroll
        for (int np = 0; np < 4; np++) {
            unsigned r0, r1, r2, r3;
            ldsm4(smem_u32(s + OFF_WHI + (brow + np * 16) * KPAD + bcol), r0, r1, r2, r3);
            bhi[2 * np][0] = r0; bhi[2 * np][1] = r1;
            bhi[2 * np + 1][0] = r2; bhi[2 * np + 1][1] = r3;
            ldsm4(smem_u32(s + OFF_WLO + (brow + np * 16) * KPAD + bcol), r0, r1, r2, r3);
            blo[2 * np][0] = r0; blo[2 * np][1] = r1;
            blo[2 * np + 1][0] = r2; blo[2 * np + 1][1] = r3;
        }
#pragma unroll
        for (int mt = 0; mt < 2; mt++)
#pragma unroll
            for (int nf = 0; nf < 8; nf++) {
                mma16816(acc[mt][nf], ahi[mt], bhi[nf]);
                mma16816(acc[mt][nf], ahi[mt], blo[nf]);
                mma16816(acc[mt][nf], alo[mt], bhi[nf]);
            }
    }
}

// full mainloop: fills acc for this block's 128x128 tile
__device__ __forceinline__ void hmma_mainloop(
    const bf16* pA0h, const bf16* pA0l, const bf16* pA1h, const bf16* pA1l,
    const bf16* pW0h, const bf16* pW0l, const bf16* pW1h, const bf16* pW1l,
    float acc[2][8][4])
{
    extern __shared__ bf16 sbuf[];
    const int t = threadIdx.x;
    const int wid = t >> 5, lane = t & 31;
    const int wm = wid & 3, wn = wid >> 2;

#pragma unroll
    for (int i = 0; i < 2; i++)
#pragma unroll
        for (int j = 0; j < 8; j++)
#pragma unroll
            for (int v = 0; v < 4; v++) acc[i][j][v] = 0.f;

    load_slab(sbuf, pA0h, pA0l, pA1h, pA1l, pW0h, pW0l, pW1h, pW1l, 0, t);
    __syncthreads();
    for (int sl = 0; sl < 24; sl++) {
        if (sl + 1 < 24)
            load_slab(sbuf + ((sl + 1) & 1) * STAGE_E,
                      pA0h, pA0l, pA1h, pA1l, pW0h, pW0l, pW1h, pW1l,
                      (sl + 1) * 32, t);
        hmma_slab(sbuf + (sl & 1) * STAGE_E, wm, wn, lane, acc);
        __syncthreads();
    }
}

// ---------------------------------------------------------------------------
// GEMM 1: Q = X @ Wq^T -> g_qhi/g_qlo (split bf16), grid (99, 6)
// ---------------------------------------------------------------------------
__global__ __launch_bounds__(256) void gemm_q_hmma()
{
    const int t = threadIdx.x;
    const int row0 = blockIdx.x * 128, col0 = blockIdx.y * 128;
    const int wid = t >> 5, lane = t & 31;
    const int wm = wid & 3, wn = wid >> 2;

    const int rA0 = row0 + (t >> 2), rA1 = rA0 + 64;
    const int cW0 = col0 + (t >> 2), cW1 = cW0 + 64;
    const bf16* pA0h = (rA0 < ROWSn) ? g_xhi + (size_t)rA0 * CC : nullptr;
    const bf16* pA0l = (rA0 < ROWSn) ? g_xlo + (size_t)rA0 * CC : nullptr;
    const bf16* pA1h = (rA1 < ROWSn) ? g_xhi + (size_t)rA1 * CC : nullptr;
    const bf16* pA1l = (rA1 < ROWSn) ? g_xlo + (size_t)rA1 * CC : nullptr;

    float acc[2][8][4];
    hmma_mainloop(pA0h, pA0l, pA1h, pA1l,
                  g_wqhi + (size_t)cW0 * CC, g_wqlo + (size_t)cW0 * CC,
                  g_wqhi + (size_t)cW1 * CC, g_wqlo + (size_t)cW1 * CC, acc);

    const int quad = lane >> 2, qp = lane & 3;
#pragma unroll
    for (int mt = 0; mt < 2; mt++)
#pragma unroll
        for (int nf = 0; nf < 8; nf++) {
            int r = row0 + wm * 32 + mt * 16 + quad;
            int c = col0 + wn * 64 + nf * 8 + qp * 2;
            __nv_bfloat162 h, l;
            if (r < ROWSn) {
                split2f(acc[mt][nf][0], acc[mt][nf][1], h, l);
                *(__nv_bfloat162*)&g_qhi[(size_t)r * CC + c] = h;
                *(__nv_bfloat162*)&g_qlo[(size_t)r * CC + c] = l;
            }
            if (r + 8 < ROWSn) {
                split2f(acc[mt][nf][2], acc[mt][nf][3], h, l);
                *(__nv_bfloat162*)&g_qhi[(size_t)(r + 8) * CC + c] = h;
                *(__nv_bfloat162*)&g_qlo[(size_t)(r + 8) * CC + c] = l;
            }
        }
}

// ---------------------------------------------------------------------------
// GEMM 2: gathered K/V projection (1632 x 1536, K=768), grid (13, 12)
// K -> g_khi/g_klo [bh][m][d], V -> g_vthi/g_vtlo [bh][d][m] (transposed)
// ---------------------------------------------------------------------------
__global__ __launch_bounds__(256) void gemm_kv_hmma()
{
    const int t = threadIdx.x;
    const int row0 = blockIdx.x * 128, col0 = blockIdx.y * 128;
    const int wid = t >> 5, lane = t & 31;
    const int wm = wid & 3, wn = wid >> 2;

    const bf16* pA[2][2] = {{nullptr, nullptr}, {nullptr, nullptr}};
#pragma unroll
    for (int i = 0; i < 2; i++) {
        int gr = row0 + (t >> 2) + i * 64;
        if (gr < GRn) {
            int b = gr / MMn, m = gr - b * MMn;
            size_t src = (size_t)(b * NNt + token_of(m)) * CC;
            pA[i][0] = g_xhi + src; pA[i][1] = g_xlo + src;
        }
    }
    const int cW0 = col0 + (t >> 2), cW1 = cW0 + 64;
    const bf16* wbase_h = g_wqhi + (size_t)768 * CC;   // k/v weight rows
    const bf16* wbase_l = g_wqlo + (size_t)768 * CC;

    float acc[2][8][4];
    hmma_mainloop(pA[0][0], pA[0][1], pA[1][0], pA[1][1],
                  wbase_h + (size_t)cW0 * CC, wbase_l + (size_t)cW0 * CC,
                  wbase_h + (size_t)cW1 * CC, wbase_l + (size_t)cW1 * CC, acc);

    const int quad = lane >> 2, qp = lane & 3;
#pragma unroll
    for (int mt = 0; mt < 2; mt++)
#pragma unroll
        for (int nf = 0; nf < 8; nf++) {
#pragma unroll
            for (int up = 0; up < 2; up++) {
                int gr = row0 + wm * 32 + mt * 16 + quad + up * 8;
                if (gr >= GRn) continue;
                int b = gr / MMn, m = gr - b * MMn;
                int c = col0 + wn * 64 + nf * 8 + qp * 2;
                float vx = acc[mt][nf][2 * up], vy = acc[mt][nf][2 * up + 1];
                if (c < 768) {
                    int h = c >> 6, d = c & 63;
                    int bh = b * HHn + h;
                    __nv_bfloat162 hh, ll;
                    split2f(vx, vy, hh, ll);
                    size_t g = ((size_t)bh * MMn + m) * HDn + d;
                    *(__nv_bfloat162*)&g_khi[g] = hh;
                    *(__nv_bfloat162*)&g_klo[g] = ll;
                } else {
                    int c2 = c - 768;
                    int h = c2 >> 6, d = c2 & 63;
                    int bh = b * HHn + h;
                    bf16 h0 = __float2bfloat16(vx);
                    bf16 h1 = __float2bfloat16(vy);
                    bf16 l0 = __float2bfloat16(vx - __bfloat162float(h0));
                    bf16 l1 = __float2bfloat16(vy - __bfloat162float(h1));
                    size_t g0 = ((size_t)bh * HDn + d) * VPP + m;
                    size_t g1 = ((size_t)bh * HDn + d + 1) * VPP + m;
                    g_vthi[g0] = h0; g_vtlo[g0] = l0;
                    g_vthi[g1] = h1; g_vtlo[g1] = l1;
                }
            }
        }
}

// ---------------------------------------------------------------------------
// Attention (tensor): one block = (bh, 128-query tile). grid (96, 13).
// Phase A: S = Q K^T (split HMMA, warps 8m x 1n, S in regs 26 frags)
// Phase B: mask, exp, quad row-sum, normalize, split-P -> smem (aliased)
// Phase C: O = P V^T (split HMMA, warps 4m x 2n), epilogue writes g_ohi/olo
// ---------------------------------------------------------------------------
__global__ __launch_bounds__(256) void attn_hmma()
{
    extern __shared__ bf16 sb[];
    const int bh = blockIdx.x, qt = blockIdx.y;
    const int b = bh / HHn, h = bh % HHn;
    const int n0 = qt * 128;
    const int t = threadIdx.x, wid = t >> 5, lane = t & 31;

    // --- loads ---
    // Q tile: 128 x 64, rows clamped
    for (int i = t; i < 1024; i += 256) {
        int row = i >> 3, u = (i & 7) * 8;
        int qn = n0 + row; if (qn >= NNt) qn = NNt - 1;
        size_t g = (size_t)(b * NNt + qn) * CC + h * HDn + u;
        *(uint4*)(sb + SQHI + row * QKP + u) = *(const uint4*)(g_qhi + g);
        *(uint4*)(sb + SQLO + row * QKP + u) = *(const uint4*)(g_qlo + g);
    }
    // K tile: 208 x 64 (rows >= 204 zeroed)
    const uint4 z4 = make_uint4(0, 0, 0, 0);
    for (int i = t; i < 1664; i += 256) {
        int row = i >> 3, u = (i & 7) * 8;
        uint4 vh = z4, vl = z4;
        if (row < MMn) {
            size_t g = ((size_t)bh * MMn + row) * HDn + u;
            vh = *(const uint4*)(g_khi + g);
            vl = *(const uint4*)(g_klo + g);
        }
        *(uint4*)(sb + SKHI + row * QKP + u) = vh;
        *(uint4*)(sb + SKLO + row * QKP + u) = vl;
    }
    // Vt tile: 64 x 216 (gmem already padded + pad zeroed)
    for (int i = t; i < 1728; i += 256) {
        int row = i / 27, u = (i % 27) * 8;
        size_t g = ((size_t)bh * HDn + row) * VPP + u;
        *(uint4*)(sb + SVHI + row * VPP + u) = *(const uint4*)(g_vthi + g);
        *(uint4*)(sb + SVLO + row * VPP + u) = *(const uint4*)(g_vtlo + g);
    }
    __syncthreads();

    // --- Phase A: S = Q K^T, warp owns 16 rows, all 208 key cols ---
    float sacc[26][4];
#pragma unroll
    for (int i = 0; i < 26; i++)
#pragma unroll
        for (int v = 0; v < 4; v++) sacc[i][v] = 0.f;

    const int m0 = wid * 16;
#pragma unroll
    for (int ks = 0; ks < 4; ks++) {
        unsigned ah[4], al[4];
        const int arow = m0 + (lane & 15);
        const int acol = ks * 16 + (lane >> 4) * 8;
        ldsm4(smem_u32(sb + SQHI + arow * QKP + acol), ah[0], ah[1], ah[2], ah[3]);
        ldsm4(smem_u32(sb + SQLO + arow * QKP + acol), al[0], al[1], al[2], al[3]);
        const int brow_base = (lane & 7) + ((lane >> 4) << 3);
        const int bcol = ks * 16 + ((lane >> 3) & 1) * 8;
#pragma unroll
        for (int np = 0; np < 13; np++) {
            unsigned kh[4], kl[4];
            ldsm4(smem_u32(sb + SKHI + (np * 16 + brow_base) * QKP + bcol),
                  kh[0], kh[1], kh[2], kh[3]);
            ldsm4(smem_u32(sb + SKLO + (np * 16 + brow_base) * QKP + bcol),
                  kl[0], kl[1], kl[2], kl[3]);
            mma16816(sacc[2 * np],     ah, kh);
            mma16816(sacc[2 * np],     ah, kl);
            mma16816(sacc[2 * np],     al, kh);
            mma16816(sacc[2 * np + 1], ah, kh + 2);
            mma16816(sacc[2 * np + 1], ah, kl + 2);
            mma16816(sacc[2 * np + 1], al, kh + 2);
        }
    }
    __syncthreads();   // all Q/K smem reads done before P overwrites the region

    // --- Phase B: mask + softmax + normalize + split-P store ---
    const int ra = m0 + (lane >> 2);
    int qa = n0 + ra, qb = qa + 8;
    int qac = qa < NNt ? qa : NNt - 1;
    int qbc = qb < NNt ? qb : NNt - 1;
    int fa = qac / NO, fb = qbc / NO;
    int csa = (fa < 4) ? (8 + 25 * fa) : (108 + 24 * (fa - 4));
    int cea = csa + ((fa < 4) ? 25 : 24);
    int csb = (fb < 4) ? (8 + 25 * fb) : (108 + 24 * (fb - 4));
    int ceb = csb + ((fb < 4) ? 25 : 24);

    float suma = 0.f, sumb = 0.f;
#pragma unroll
    for (int nf = 0; nf < 26; nf++) {
        int c0 = nf * 8 + (lane & 3) * 2;
        int c1 = c0 + 1;
        float ma0 = (c0 < 8 || (c0 >= csa && c0 < cea)) ? 0.125f : 0.1f;
        float ma1 = (c1 < 8 || (c1 >= csa && c1 < cea)) ? 0.125f : 0.1f;
        float mb0 = (c0 < 8 || (c0 >= csb && c0 < ceb)) ? 0.125f : 0.1f;
        float mb1 = (c1 < 8 || (c1 >= csb && c1 < ceb)) ? 0.125f : 0.1f;
        float pa0 = (c0 < MMn) ? __expf(sacc[nf][0] * ma0) : 0.f;
        float pa1 = (c1 < MMn) ? __expf(sacc[nf][1] * ma1) : 0.f;
        float pb0 = (c0 < MMn) ? __expf(sacc[nf][2] * mb0) : 0.f;
        float pb1 = (c1 < MMn) ? __expf(sacc[nf][3] * mb1) : 0.f;
        sacc[nf][0] = pa0; sacc[nf][1] = pa1;
        sacc[nf][2] = pb0; sacc[nf][3] = pb1;
        suma += pa0 + pa1; sumb += pb0 + pb1;
    }
    suma += __shfl_xor_sync(0xffffffffu, suma, 1);
    suma += __shfl_xor_sync(0xffffffffu, suma, 2);
    sumb += __shfl_xor_sync(0xffffffffu, sumb, 1);
    sumb += __shfl_xor_sync(0xffffffffu, sumb, 2);
    const float inva = 1.f / suma, invb = 1.f / sumb;

#pragma unroll
    for (int nf = 0; nf < 26; nf++) {
        int c0 = nf * 8 + (lane & 3) * 2;
        __nv_bfloat162 hh, ll;
        split2f(sacc[nf][0] * inva, sacc[nf][1] * inva, hh, ll);
        *(__nv_bfloat162*)(sb + SPHI + ra * VPP + c0) = hh;
        *(__nv_bfloat162*)(sb + SPLO + ra * VPP + c0) = ll;
        split2f(sacc[nf][2] * invb, sacc[nf][3] * invb, hh, ll);
        *(__nv_bfloat162*)(sb + SPHI + (ra + 8) * VPP + c0) = hh;
        *(__nv_bfloat162*)(sb + SPLO + (ra + 8) * VPP + c0) = ll;
    }
    __syncthreads();

    // --- Phase C: O = P V^T. warps 4m x 2n, warp tile 32x32, K=208 ---
    const int wm = wid & 3, wn = wid >> 2;
    float oacc[2][4][4];
#pragma unroll
    for (int i = 0; i < 2; i++)
#pragma unroll
        for (int j = 0; j < 4; j++)
#pragma unroll
            for (int v = 0; v < 4; v++) oacc[i][j][v] = 0.f;

#pragma unroll 1
    for (int kk = 0; kk < 13; kk++) {
        unsigned ph[2][4], pl[2][4];
        const int acol = kk * 16 + (lane >> 4) * 8;
#pragma unroll
        for (int mt = 0; mt < 2; mt++) {
            const int arow = wm * 32 + mt * 16 + (lane & 15);
            ldsm4(smem_u32(sb + SPHI + arow * VPP + acol),
                  ph[mt][0], ph[mt][1], ph[mt][2], ph[mt][3]);
            ldsm4(smem_u32(sb + SPLO + arow * VPP + acol),
                  pl[mt][0], pl[mt][1], pl[mt][2], pl[mt][3]);
        }
        unsigned vh[4][2], vl[4][2];
        const int brow_base = wn * 32 + (lane & 7) + ((lane >> 4) << 3);
        const int bcol = kk * 16 + ((lane >> 3) & 1) * 8;
#pragma unroll
        for (int np = 0; np < 2; np++) {
            unsigned r0, r1, r2, r3;
            ldsm4(smem_u32(sb + SVHI + (brow_base + np * 16) * VPP + bcol), r0, r1, r2, r3);
            vh[2 * np][0] = r0; vh[2 * np][1] = r1;
            vh[2 * np + 1][0] = r2; vh[2 * np + 1][1] = r3;
            ldsm4(smem_u32(sb + SVLO + (brow_base + np * 16) * VPP + bcol), r0, r1, r2, r3);
            vl[2 * np][0] = r0; vl[2 * np][1] = r1;
            vl[2 * np + 1][0] = r2; vl[2 * np + 1][1] = r3;
        }
#pragma unroll
        for (int mt = 0; mt < 2; mt++)
#pragma unroll
            for (int nf = 0; nf < 4; nf++) {
                mma16816(oacc[mt][nf], ph[mt], vh[nf]);
                mma16816(oacc[mt][nf], pl[mt], vh[nf]);
                mma16816(oacc[mt][nf], ph[mt], vl[nf]);
            }
    }

    // epilogue: split O directly to g_ohi/g_olo (token-major [row][CC])
    const int quad = lane >> 2, qp = lane & 3;
#pragma unroll
    for (int mt = 0; mt < 2; mt++)
#pragma unroll
        for (int nf = 0; nf < 4; nf++) {
            int r = n0 + wm * 32 + mt * 16 + quad;
            int c = h * HDn + wn * 32 + nf * 8 + qp * 2;
            __nv_bfloat162 hh, ll;
            if (r < NNt) {
                size_t g = (size_t)(b * NNt + r) * CC + c;
                split2f(oacc[mt][nf][0], oacc[mt][nf][1], hh, ll);
                *(__nv_bfloat162*)&g_ohi[g] = hh;
                *(__nv_bfloat162*)&g_olo[g] = ll;
            }
            if (r + 8 < NNt) {
                size_t g = (size_t)(b * NNt + r + 8) * CC + c;
                split2f(oacc[mt][nf][2], oacc[mt][nf][3], hh, ll);
                *(__nv_bfloat162*)&g_ohi[g] = hh;
                *(__nv_bfloat162*)&g_olo[g] = ll;
            }
        }
}

// ---------------------------------------------------------------------------
// GEMM 3: out = O @ proj_w^T + proj_b   (12608 x 768, K=768), grid (99, 6)
// ---------------------------------------------------------------------------
__global__ __launch_bounds__(256) void gemm_proj_hmma(
    const float* __restrict__ bias, float* __restrict__ Cout)
{
    const int t = threadIdx.x;
    const int row0 = blockIdx.x * 128, col0 = blockIdx.y * 128;
    const int wid = t >> 5, lane = t & 31;
    const int wm = wid & 3, wn = wid >> 2;

    const int rA0 = row0 + (t >> 2), rA1 = rA0 + 64;
    const int cW0 = col0 + (t >> 2), cW1 = cW0 + 64;
    const bf16* pA0h = (rA0 < ROWSn) ? g_ohi + (size_t)rA0 * CC : nullptr;
    const bf16* pA0l = (rA0 < ROWSn) ? g_olo + (size_t)rA0 * CC : nullptr;
    const bf16* pA1h = (rA1 < ROWSn) ? g_ohi + (size_t)rA1 * CC : nullptr;
    const bf16* pA1l = (rA1 < ROWSn) ? g_olo + (size_t)rA1 * CC : nullptr;

    float acc[2][8][4];
    hmma_mainloop(pA0h, pA0l, pA1h, pA1l,
                  g_wphi + (size_t)cW0 * CC, g_wplo + (size_t)cW0 * CC,
                  g_wphi + (size_t)cW1 * CC, g_wplo + (size_t)cW1 * CC, acc);

    const int quad = lane >> 2, qp = lane & 3;
#pragma unroll
    for (int nf = 0; nf < 8; nf++) {
        int c = col0 + wn * 64 + nf * 8 + qp * 2;
        float2 bv = *(const float2*)&bias[c];
#pragma unroll
        for (int mt = 0; mt < 2; mt++) {
            int r = row0 + wm * 32 + mt * 16 + quad;
            if (r < ROWSn)
                *(float2*)&Cout[(size_t)r * CC + c] =
                    make_float2(acc[mt][nf][0] + bv.x, acc[mt][nf][1] + bv.y);
            if (r + 8 < ROWSn)
                *(float2*)&Cout[(size_t)(r + 8) * CC + c] =
                    make_float2(acc[mt][nf][2] + bv.x, acc[mt][nf][3] + bv.y);
        }
    }
}

// ---------------------------------------------------------------------------
extern "C" void kernel_launch(void* const* d_in, const int* in_sizes, int n_in,
                              void* d_out, int out_size)
{
    const float* x      = (const float*)d_in[0];
    const float* qkv_w  = (const float*)d_in[1];
    const float* proj_w = (const float*)d_in[2];
    const float* proj_b = (const float*)d_in[3];
    float* out = (float*)d_out;

    cudaFuncSetAttribute(gemm_q_hmma,
                         cudaFuncAttributeMaxDynamicSharedMemorySize, SMEM_GEMM);
    cudaFuncSetAttribute(gemm_kv_hmma,
                         cudaFuncAttributeMaxDynamicSharedMemorySize, SMEM_GEMM);
    cudaFuncSetAttribute(gemm_proj_hmma,
                         cudaFuncAttributeMaxDynamicSharedMemorySize, SMEM_GEMM);
    cudaFuncSetAttribute(attn_hmma,
                         cudaFuncAttributeMaxDynamicSharedMemorySize, SMEM_ATT);

    bf16 *xhi, *xlo, *wqhi, *wqlo, *wphi, *wplo;
    cudaGetSymbolAddress((void**)&xhi, g_xhi);
    cudaGetSymbolAddress((void**)&xlo, g_xlo);
    cudaGetSymbolAddress((void**)&wqhi, g_wqhi);
    cudaGetSymbolAddress((void**)&wqlo, g_wqlo);
    cudaGetSymbolAddress((void**)&wphi, g_wphi);
    cudaGetSymbolAddress((void**)&wplo, g_wplo);

    dim3 blk(256);
    int n4x = ROWSn * CC / 4;
    int n4q = 3 * CC * CC / 4;
    int n4p = CC * CC / 4;
    cvt_hilo<<<(n4x + 255) / 256, blk>>>(x, xhi, xlo, n4x);
    cvt_hilo<<<(n4q + 255) / 256, blk>>>(qkv_w, wqhi, wqlo, n4q);
    cvt_hilo<<<(n4p + 255) / 256, blk>>>(proj_w, wphi, wplo, n4p);
    vt_zero_pad<<<NBH, blk>>>();

    gemm_q_hmma<<<dim3(99, 6), blk, SMEM_GEMM>>>();
    gemm_kv_hmma<<<dim3(13, 12), blk, SMEM_GEMM>>>();
    attn_hmma<<<dim3(NBH, 13), blk, SMEM_ATT>>>();
    gemm_proj_hmma<<<dim3(99, 6), blk, SMEM_GEMM>>>(proj_b, out);
}